// round 13
// baseline (speedup 1.0000x reference)
#include <cuda_runtime.h>
#include <cuda_fp16.h>
#include <math.h>
#include <stdint.h>

// Problem constants
#define Bc 128
#define Pc 196
#define Dc 2048
#define Ac 512
#define Ec 512
#define Hc 512
#define Vc 10000
#define Tc 19
#define TMAXc 20
#define G4H (4 * Hc)      // 2048 gate width
#define NDB 2560          // A + D (dec | beta)
#define NA  4608          // A + D + 4H (dec | beta | w_hh)
#define VPAD2 10112       // Vc padded to 128

// ---------------- scratch (device globals; no allocation allowed) ----------
__device__ __half g_feat16[(size_t)Bc * Pc * Dc];
__device__ __half g_meanf16[Bc * Dc];
__device__ __half g_h16[Bc * Hc];
__device__ float  g_c[Bc * Hc];
__device__ __half g_hn16[Tc][Bc * Hc];
__device__ __half g_att1_16[(size_t)Bc * Pc * Ac];
__device__ __half g_eseq16[(size_t)Bc * Tc * Ec];
__device__ float  g_att2[Bc * Ac];
__device__ float  g_alpha[Bc * Pc];
__device__ __half g_gate16[Bc * Dc];
__device__ float  g_hg[Bc * G4H];                     // h @ w_hh (per step)
__device__ float  g_egpre[(size_t)Bc * Tc * G4H];     // e_t @ W1 (all steps)
__device__ __half g_xinD[Bc * Dc];                    // gate * awe
__device__ float  g_gates[2][Bc * G4H];               // split-K partials
// transposed fp16 weights (K-major B operands: Bt[n][k])
__device__ __half g_hfcT[Hc * Dc];
__device__ __half g_cfcT[Hc * Dc];
__device__ __half g_encT[Ac * Dc];
__device__ __half g_abT[(size_t)NA * Hc];             // [decT | betaT | w_hhT]
__device__ float  g_dbbias[NDB];
__device__ __half g_w1T[(size_t)G4H * Ec];            // w_ih rows 0..511 ^T
__device__ __half g_w2T[(size_t)G4H * Dc];            // w_ih rows 512..2559 ^T
__device__ __half g_clsT[(size_t)VPAD2 * Hc];
__device__ float  g_bcat[G4H];
// software grid barrier state (R11-proven implementation)
__device__ unsigned g_bar_count = 0;
__device__ unsigned g_bar_gen = 0;

// ---------------- helpers ---------------------------------------------------
__device__ __forceinline__ uint32_t smem_u32(const void* p) {
    uint32_t a;
    asm("{ .reg .u64 t; cvta.to.shared.u64 t, %1; cvt.u32.u64 %0, t; }" : "=r"(a) : "l"(p));
    return a;
}
__device__ __forceinline__ void cp16(uint32_t dst, const void* src) {
    asm volatile("cp.async.ca.shared.global [%0], [%1], 16;" :: "r"(dst), "l"(src));
}
#define CP_COMMIT() asm volatile("cp.async.commit_group;" ::: "memory")

__device__ __forceinline__ float sigf(float x) { return 1.f / (1.f + expf(-x)); }

__device__ __forceinline__ void grid_bar(unsigned nb) {
    __syncthreads();
    if (threadIdx.x == 0) {
        __threadfence();
        unsigned gen = atomicAdd(&g_bar_gen, 0u);
        unsigned prev = atomicAdd(&g_bar_count, 1u);
        if (prev == nb - 1) {
            atomicExch(&g_bar_count, 0u);
            __threadfence();
            atomicAdd(&g_bar_gen, 1u);
        } else {
            while (atomicAdd(&g_bar_gen, 0u) == gen) __nanosleep(64);
        }
        __threadfence();
    }
    __syncthreads();
}

#define ASTR 40
struct GemmSm { __half A[2][64 * ASTR]; __half B[2][64 * ASTR]; };   // 20480 B
struct AttSm  { float s2[Ac]; float sw[Ac]; float se[224]; float red[256]; };
union SmemU { GemmSm g; AttSm a; };

// 64x64 double-buffered mma core; all 256 threads participate.
__device__ __forceinline__ void gemm_core(SmemU& sm,
    const __half* __restrict__ Ab, const __half* __restrict__ Bb,
    int nk, int lda, int ldb, float acc[2][2][4])
{
    const int tid = threadIdx.x;
    const int lane = tid & 31, warp = tid >> 5;
    const int wm = warp >> 2, wn = warp & 3;
    const uint32_t sAu = smem_u32(sm.g.A);
    const uint32_t sBu = smem_u32(sm.g.B);
    const int aRow = wm * 32 + (lane & 15);
    const int aCol = (lane >= 16) ? 8 : 0;
    const int bRow = wn * 16 + (lane & 7);
    const int bCol = ((lane & 15) >= 8) ? 8 : 0;
    const int lr = tid >> 2, lq = tid & 3;

    #pragma unroll
    for (int i = 0; i < 2; i++)
        #pragma unroll
        for (int j = 0; j < 2; j++)
            #pragma unroll
            for (int e = 0; e < 4; e++) acc[i][j][e] = 0.f;

    cp16(sAu + (uint32_t)(lr * ASTR + lq * 8) * 2, Ab + (size_t)lr * lda + lq * 8);
    cp16(sBu + (uint32_t)(lr * ASTR + lq * 8) * 2, Bb + (size_t)lr * ldb + lq * 8);
    CP_COMMIT();

    for (int i = 0; i < nk; i++) {
        int buf = i & 1;
        if (i + 1 < nk) {
            int nbuf = buf ^ 1;
            int k0 = (i + 1) << 5;
            cp16(sAu + (uint32_t)(nbuf * 64 * ASTR + lr * ASTR + lq * 8) * 2,
                 Ab + (size_t)lr * lda + k0 + lq * 8);
            cp16(sBu + (uint32_t)(nbuf * 64 * ASTR + lr * ASTR + lq * 8) * 2,
                 Bb + (size_t)lr * ldb + k0 + lq * 8);
            CP_COMMIT();
            asm volatile("cp.async.wait_group 1;" ::: "memory");
        } else {
            asm volatile("cp.async.wait_group 0;" ::: "memory");
        }
        __syncthreads();
        uint32_t baseA = sAu + (uint32_t)(buf * 64 * ASTR) * 2;
        uint32_t baseB = sBu + (uint32_t)(buf * 64 * ASTR) * 2;
        #pragma unroll
        for (int ks = 0; ks < 32; ks += 16) {
            uint32_t a[2][4], b[2][2];
            #pragma unroll
            for (int mf = 0; mf < 2; mf++) {
                uint32_t addr = baseA + (uint32_t)((aRow + mf * 16) * ASTR + ks + aCol) * 2;
                asm volatile("ldmatrix.sync.aligned.m8n8.x4.shared.b16 {%0,%1,%2,%3}, [%4];"
                             : "=r"(a[mf][0]), "=r"(a[mf][1]), "=r"(a[mf][2]), "=r"(a[mf][3])
                             : "r"(addr));
            }
            #pragma unroll
            for (int nf = 0; nf < 2; nf++) {
                uint32_t addr = baseB + (uint32_t)((bRow + nf * 8) * ASTR + ks + bCol) * 2;
                asm volatile("ldmatrix.sync.aligned.m8n8.x2.shared.b16 {%0,%1}, [%2];"
                             : "=r"(b[nf][0]), "=r"(b[nf][1]) : "r"(addr));
            }
            #pragma unroll
            for (int mf = 0; mf < 2; mf++)
                #pragma unroll
                for (int nf = 0; nf < 2; nf++) {
                    float* cc = acc[mf][nf];
                    asm volatile(
                        "mma.sync.aligned.m16n8k16.row.col.f32.f16.f16.f32 "
                        "{%0,%1,%2,%3}, {%4,%5,%6,%7}, {%8,%9}, {%0,%1,%2,%3};"
                        : "+f"(cc[0]), "+f"(cc[1]), "+f"(cc[2]), "+f"(cc[3])
                        : "r"(a[mf][0]), "r"(a[mf][1]), "r"(a[mf][2]), "r"(a[mf][3]),
                          "r"(b[nf][0]), "r"(b[nf][1]));
                }
        }
        __syncthreads();
    }
}

// ---------------- persistent step-loop kernel --------------------------------
#define AWE8 (Bc * Dc / 8)
__device__ __forceinline__ void h2acc(uint32_t h2, float a, float& x, float& y) {
    float2 v = __half22float2(*(__half2*)&h2);
    x += a * v.x;
    y += a * v.y;
}

__global__ void __launch_bounds__(256, 2) step_loop_kernel(
    const float* __restrict__ att_w, const float* __restrict__ att_b,
    const int* __restrict__ lengths, float* __restrict__ a_out)
{
    __shared__ SmemU sm;
    const int tid = threadIdx.x;
    const int lane = tid & 31, warp = tid >> 5;
    const int wm = warp >> 2, wn = warp & 3;
    const unsigned nb = gridDim.x;
    const int gsize = (int)nb * 256;
    const int gid = blockIdx.x * 256 + tid;

    for (int t = 0; t < Tc; t++) {
        // ---- Phase A: [att2 | gate | hg] = h @ abT  (N=4608, K=512) ----
        for (int u = blockIdx.x; u < 2 * (NA / 64); u += (int)nb) {
            int row0 = (u / (NA / 64)) * 64, col0 = (u % (NA / 64)) * 64;
            float acc[2][2][4];
            gemm_core(sm, g_h16 + (size_t)row0 * Hc, g_abT + (size_t)col0 * Hc,
                      Hc >> 5, Hc, Hc, acc);
            int mbase = row0 + wm * 32, nbase = col0 + wn * 16;
            #pragma unroll
            for (int mf = 0; mf < 2; mf++)
                #pragma unroll
                for (int hr = 0; hr < 2; hr++) {
                    int m = mbase + mf * 16 + (lane >> 2) + hr * 8;
                    #pragma unroll
                    for (int nf = 0; nf < 2; nf++)
                        #pragma unroll
                        for (int e = 0; e < 2; e++) {
                            int n = nbase + nf * 8 + (lane & 3) * 2 + e;
                            float v = acc[mf][nf][hr * 2 + e];
                            if (n < Ac) g_att2[m * Ac + n] = v + g_dbbias[n];
                            else if (n < NDB)
                                g_gate16[m * Dc + (n - Ac)] = __float2half_rn(sigf(v + g_dbbias[n]));
                            else g_hg[m * G4H + (n - NDB)] = v;
                        }
                }
        }
        grid_bar(nb);

        // ---- Phase B: e = relu(att1 + att2) @ att_w + att_b; softmax ----
        for (int b = blockIdx.x; b < Bc; b += (int)nb) {
            for (int i = tid; i < Ac; i += 256) {
                sm.a.s2[i] = g_att2[b * Ac + i];
                sm.a.sw[i] = att_w[i];
            }
            __syncthreads();
            float attb = att_b[0];
            for (int p = warp; p < Pc; p += 8) {
                const __half2* a1 = (const __half2*)(g_att1_16 + ((size_t)b * Pc + p) * Ac);
                float s = 0.f;
                #pragma unroll
                for (int k = 0; k < 8; k++) {
                    int h2i = lane + 32 * k;
                    float2 v = __half22float2(a1[h2i]);
                    int a0 = 2 * h2i;
                    s += fmaxf(v.x + sm.a.s2[a0], 0.f) * sm.a.sw[a0];
                    s += fmaxf(v.y + sm.a.s2[a0 + 1], 0.f) * sm.a.sw[a0 + 1];
                }
                #pragma unroll
                for (int o = 16; o > 0; o >>= 1) s += __shfl_xor_sync(0xffffffffu, s, o);
                if (lane == 0) sm.a.se[p] = s + attb;
            }
            __syncthreads();
            float v = (tid < Pc) ? sm.a.se[tid] : -1e30f;
            sm.a.red[tid] = v;
            __syncthreads();
            for (int s = 128; s > 0; s >>= 1) {
                if (tid < s) sm.a.red[tid] = fmaxf(sm.a.red[tid], sm.a.red[tid + s]);
                __syncthreads();
            }
            float mx = sm.a.red[0];
            __syncthreads();
            float ex = (tid < Pc) ? expf(v - mx) : 0.f;
            sm.a.red[tid] = ex;
            __syncthreads();
            for (int s = 128; s > 0; s >>= 1) {
                if (tid < s) sm.a.red[tid] += sm.a.red[tid + s];
                __syncthreads();
            }
            float inv = 1.0f / sm.a.red[0];
            if (tid < Pc) {
                float al = ex * inv;
                g_alpha[b * Pc + tid] = al;
                float mf = (t < lengths[b] - 1) ? 1.f : 0.f;
                a_out[((size_t)b * Tc + t) * Pc + tid] = al * mf;
            }
            __syncthreads();
        }
        grid_bar(nb);

        // ---- Phase C: xinD = gate * (alpha @ features) ----
        for (int idx = gid; idx < AWE8; idx += gsize) {
            int b = idx / (Dc / 8), d8 = idx % (Dc / 8);
            const uint4* fp = ((const uint4*)g_feat16) + (size_t)b * Pc * (Dc / 8) + d8;
            const float* al = g_alpha + b * Pc;
            float s[8] = {0.f, 0.f, 0.f, 0.f, 0.f, 0.f, 0.f, 0.f};
            #pragma unroll 4
            for (int p = 0; p < Pc; p++) {
                float a = al[p];
                uint4 vv = fp[(size_t)p * (Dc / 8)];
                h2acc(vv.x, a, s[0], s[1]);
                h2acc(vv.y, a, s[2], s[3]);
                h2acc(vv.z, a, s[4], s[5]);
                h2acc(vv.w, a, s[6], s[7]);
            }
            uint4 g4 = ((const uint4*)g_gate16)[b * (Dc / 8) + d8];
            float2 g0 = __half22float2(*(__half2*)&g4.x);
            float2 g1 = __half22float2(*(__half2*)&g4.y);
            float2 g2 = __half22float2(*(__half2*)&g4.z);
            float2 g3 = __half22float2(*(__half2*)&g4.w);
            __half2 r0 = __floats2half2_rn(s[0] * g0.x, s[1] * g0.y);
            __half2 r1 = __floats2half2_rn(s[2] * g1.x, s[3] * g1.y);
            __half2 r2 = __floats2half2_rn(s[4] * g2.x, s[5] * g2.y);
            __half2 r3 = __floats2half2_rn(s[6] * g3.x, s[7] * g3.y);
            uint4 r;
            r.x = *(uint32_t*)&r0; r.y = *(uint32_t*)&r1;
            r.z = *(uint32_t*)&r2; r.w = *(uint32_t*)&r3;
            ((uint4*)g_xinD)[b * (Dc / 8) + d8] = r;
        }
        grid_bar(nb);

        // ---- Phase D: gates partials = xinD @ w2T (K=2048, split 2) ----
        for (int u = blockIdx.x; u < 2 * 32 * 2; u += (int)nb) {
            int z = u & 1, uu = u >> 1;
            int row0 = (uu / 32) * 64, col0 = (uu % 32) * 64;
            float acc[2][2][4];
            gemm_core(sm, g_xinD + (size_t)row0 * Dc + z * (Dc / 2),
                      g_w2T + (size_t)col0 * Dc + z * (Dc / 2),
                      (Dc / 2) >> 5, Dc, Dc, acc);
            int mbase = row0 + wm * 32, nbase = col0 + wn * 16;
            float* gz = g_gates[z];
            #pragma unroll
            for (int mf = 0; mf < 2; mf++)
                #pragma unroll
                for (int hr = 0; hr < 2; hr++) {
                    int m = mbase + mf * 16 + (lane >> 2) + hr * 8;
                    #pragma unroll
                    for (int nf = 0; nf < 2; nf++)
                        #pragma unroll
                        for (int e = 0; e < 2; e++) {
                            int n = nbase + nf * 8 + (lane & 3) * 2 + e;
                            gz[(size_t)m * G4H + n] = acc[mf][nf][hr * 2 + e];
                        }
                }
        }
        grid_bar(nb);

        // ---- Phase E: LSTM pointwise ----
        for (int idx = gid; idx < Bc * Hc; idx += gsize) {
            int b = idx / Hc, j = idx % Hc;
            const float* ep = g_egpre + ((size_t)b * Tc + t) * G4H;
            const float* hp = g_hg + (size_t)b * G4H;
            const float* p0 = g_gates[0] + (size_t)b * G4H;
            const float* p1 = g_gates[1] + (size_t)b * G4H;
            float i_ = g_bcat[j]          + ep[j]          + hp[j]          + p0[j]          + p1[j];
            float f_ = g_bcat[Hc + j]     + ep[Hc + j]     + hp[Hc + j]     + p0[Hc + j]     + p1[Hc + j];
            float gg = g_bcat[2 * Hc + j] + ep[2 * Hc + j] + hp[2 * Hc + j] + p0[2 * Hc + j] + p1[2 * Hc + j];
            float o_ = g_bcat[3 * Hc + j] + ep[3 * Hc + j] + hp[3 * Hc + j] + p0[3 * Hc + j] + p1[3 * Hc + j];
            float cn = sigf(f_) * g_c[idx] + sigf(i_) * tanhf(gg);
            float hn = sigf(o_) * tanhf(cn);
            g_hn16[t][idx] = __float2half_rn(hn);
            if (t < lengths[b] - 1) {
                g_h16[idx] = __float2half_rn(hn);
                g_c[idx] = cn;
            }
        }
        grid_bar(nb);
    }
}

// ---------------- template GEMM for prologue + batched cls -------------------
// mode 0: plain bias (+C/C16). mode 3: batched cls (row m -> t=m>>7, b=m&127).
template<int BM, int BN>
__global__ void __launch_bounds__(256) gemm_mma(
    const __half* __restrict__ A, const __half* __restrict__ Bt,
    const float* __restrict__ bias, float* __restrict__ C, __half* __restrict__ C16,
    int M, int N, int K, int ldc, int ld16, int mode,
    const int* __restrict__ lengths)
{
    constexpr int MFRAG = BM / 32;
    constexpr int NFRAG = BN / 32;
    __shared__ __half sA[2][BM * ASTR];
    __shared__ __half sB[2][BN * ASTR];

    const int tid = threadIdx.x;
    const int lane = tid & 31, warp = tid >> 5;
    const int wm = warp >> 2, wn = warp & 3;
    const int row0 = blockIdx.y * BM, col0 = blockIdx.x * BN;

    const __half* Ab = A + (size_t)row0 * K;
    const __half* Bb = Bt + (size_t)col0 * K;
    const int nk = K >> 5;

    const uint32_t sAu = smem_u32(sA);
    const uint32_t sBu = smem_u32(sB);

    float acc[MFRAG][NFRAG][4];
    #pragma unroll
    for (int i = 0; i < MFRAG; i++)
        #pragma unroll
        for (int j = 0; j < NFRAG; j++)
            #pragma unroll
            for (int e = 0; e < 4; e++) acc[i][j][e] = 0.f;

    const int aRow = wm * (BM / 2) + (lane & 15);
    const int aCol = (lane >= 16) ? 8 : 0;
    const int bRow = wn * (BN / 4) + (lane & 7);
    const int bCol = ((lane & 15) >= 8) ? 8 : 0;

    {
        #pragma unroll
        for (int l = 0; l < BM / 64; l++) {
            int c = tid + l * 256;
            int r = c >> 2, q = c & 3;
            cp16(sAu + (uint32_t)(r * ASTR + q * 8) * 2, Ab + (size_t)r * K + q * 8);
        }
        #pragma unroll
        for (int l = 0; l < BN / 64; l++) {
            int c = tid + l * 256;
            int r = c >> 2, q = c & 3;
            cp16(sBu + (uint32_t)(r * ASTR + q * 8) * 2, Bb + (size_t)r * K + q * 8);
        }
    }
    CP_COMMIT();

    for (int i = 0; i < nk; i++) {
        int buf = i & 1;
        if (i + 1 < nk) {
            int nbuf = buf ^ 1;
            int k0 = (i + 1) << 5;
            #pragma unroll
            for (int l = 0; l < BM / 64; l++) {
                int c = tid + l * 256;
                int r = c >> 2, q = c & 3;
                cp16(sAu + (uint32_t)(nbuf * BM * ASTR + r * ASTR + q * 8) * 2,
                     Ab + (size_t)r * K + k0 + q * 8);
            }
            #pragma unroll
            for (int l = 0; l < BN / 64; l++) {
                int c = tid + l * 256;
                int r = c >> 2, q = c & 3;
                cp16(sBu + (uint32_t)(nbuf * BN * ASTR + r * ASTR + q * 8) * 2,
                     Bb + (size_t)r * K + k0 + q * 8);
            }
            CP_COMMIT();
            asm volatile("cp.async.wait_group 1;" ::: "memory");
        } else {
            asm volatile("cp.async.wait_group 0;" ::: "memory");
        }
        __syncthreads();

        uint32_t baseA = sAu + (uint32_t)(buf * BM * ASTR) * 2;
        uint32_t baseB = sBu + (uint32_t)(buf * BN * ASTR) * 2;
        #pragma unroll
        for (int ks = 0; ks < 32; ks += 16) {
            uint32_t a[MFRAG][4], b[NFRAG][2];
            #pragma unroll
            for (int mf = 0; mf < MFRAG; mf++) {
                uint32_t addr = baseA + (uint32_t)((aRow + mf * 16) * ASTR + ks + aCol) * 2;
                asm volatile("ldmatrix.sync.aligned.m8n8.x4.shared.b16 {%0,%1,%2,%3}, [%4];"
                             : "=r"(a[mf][0]), "=r"(a[mf][1]), "=r"(a[mf][2]), "=r"(a[mf][3])
                             : "r"(addr));
            }
            #pragma unroll
            for (int nf = 0; nf < NFRAG; nf++) {
                uint32_t addr = baseB + (uint32_t)((bRow + nf * 8) * ASTR + ks + bCol) * 2;
                asm volatile("ldmatrix.sync.aligned.m8n8.x2.shared.b16 {%0,%1}, [%2];"
                             : "=r"(b[nf][0]), "=r"(b[nf][1]) : "r"(addr));
            }
            #pragma unroll
            for (int mf = 0; mf < MFRAG; mf++)
                #pragma unroll
                for (int nf = 0; nf < NFRAG; nf++) {
                    float* cc = acc[mf][nf];
                    asm volatile(
                        "mma.sync.aligned.m16n8k16.row.col.f32.f16.f16.f32 "
                        "{%0,%1,%2,%3}, {%4,%5,%6,%7}, {%8,%9}, {%0,%1,%2,%3};"
                        : "+f"(cc[0]), "+f"(cc[1]), "+f"(cc[2]), "+f"(cc[3])
                        : "r"(a[mf][0]), "r"(a[mf][1]), "r"(a[mf][2]), "r"(a[mf][3]),
                          "r"(b[nf][0]), "r"(b[nf][1]));
                }
        }
        __syncthreads();
    }

    const int mbase = row0 + wm * (BM / 2);
    const int nbase = col0 + wn * (BN / 4);
    #pragma unroll
    for (int mf = 0; mf < MFRAG; mf++) {
        #pragma unroll
        for (int hr = 0; hr < 2; hr++) {
            int m = mbase + mf * 16 + (lane >> 2) + hr * 8;
            #pragma unroll
            for (int nf = 0; nf < NFRAG; nf++) {
                #pragma unroll
                for (int e = 0; e < 2; e++) {
                    int n = nbase + nf * 8 + (lane & 3) * 2 + e;
                    if (n < N) {
                        float v = acc[mf][nf][hr * 2 + e];
                        if (bias) v += bias[n];
                        if (mode == 3) {
                            int tt = m >> 7, bb = m & 127;
                            float mk = (tt < lengths[bb] - 1) ? 1.f : 0.f;
                            C[((size_t)bb * Tc + tt) * Vc + n] = v * mk;
                        } else {
                            if (C)   C[(size_t)m * ldc + n] = v;
                            if (C16) C16[(size_t)m * ld16 + n] = __float2half_rn(v);
                        }
                    }
                }
            }
        }
    }
}

// ---------------- support kernels -------------------------------------------

__global__ void f32to16_kernel(const float* __restrict__ in, __half* __restrict__ out, int n2) {
    int i = blockIdx.x * blockDim.x + threadIdx.x;
    if (i < n2) {
        float2 v = ((const float2*)in)[i];
        ((__half2*)out)[i] = __floats2half2_rn(v.x, v.y);
    }
}

__global__ void transpose16_kernel(const float* __restrict__ in, __half* __restrict__ out,
                                   int K, int N, int out_ld, int k_off) {
    __shared__ float tile[32][33];
    int kb = blockIdx.y * 32, nb = blockIdx.x * 32;
    int x = threadIdx.x, y = threadIdx.y;
    #pragma unroll
    for (int j = 0; j < 32; j += 8) {
        int k = kb + y + j, n = nb + x;
        tile[y + j][x] = (k < K && n < N) ? in[(size_t)k * N + n] : 0.f;
    }
    __syncthreads();
    #pragma unroll
    for (int j = 0; j < 32; j += 8) {
        int n = nb + y + j, k = kb + x;
        if (n < N && k < K) out[(size_t)n * out_ld + k_off + k] = __float2half_rn(tile[x][y + j]);
    }
}

__global__ void clspad_kernel() {
    int i = blockIdx.x * blockDim.x + threadIdx.x;
    int total = (VPAD2 - Vc) * Hc;
    if (i < total) g_clsT[(size_t)Vc * Hc + i] = __float2half_rn(0.f);
}

__global__ void bias_prep_kernel(const float* __restrict__ bi, const float* __restrict__ bh,
                                 const float* __restrict__ db, const float* __restrict__ bb) {
    int i = blockIdx.x * blockDim.x + threadIdx.x;
    if (i < G4H) g_bcat[i] = bi[i] + bh[i];
    if (i < NDB) g_dbbias[i] = (i < Ac) ? db[i] : bb[i - Ac];
}

__global__ void mean_kernel(const float* __restrict__ f) {
    int idx = blockIdx.x * blockDim.x + threadIdx.x;
    if (idx >= Bc * Dc) return;
    int b = idx / Dc, d = idx % Dc;
    const float* p = f + (size_t)b * Pc * Dc + d;
    float s = 0.f;
    #pragma unroll 4
    for (int i = 0; i < Pc; i++) s += p[(size_t)i * Dc];
    g_meanf16[idx] = __float2half_rn(s * (1.0f / Pc));
}

__global__ void embed_kernel(const float* __restrict__ emb, const int* __restrict__ cap) {
    int idx = blockIdx.x * blockDim.x + threadIdx.x;
    if (idx >= Bc * Tc * Ec) return;
    int j = idx % Ec;
    int bt = idx / Ec;
    int t = bt % Tc;
    int b = bt / Tc;
    int tok = cap[b * TMAXc + t];
    g_eseq16[idx] = __float2half_rn(emb[(size_t)tok * Ec + j]);
}

// ---------------- launcher ---------------------------------------------------

static void transL(const float* in, __half* out, int K, int N, int out_ld, int k_off) {
    dim3 grid((N + 31) / 32, (K + 31) / 32);
    transpose16_kernel<<<grid, dim3(32, 8)>>>(in, out, K, N, out_ld, k_off);
}

extern "C" void kernel_launch(void* const* d_in, const int* in_sizes, int n_in,
                              void* d_out, int out_size) {
    const float* features = (const float*)d_in[0];
    const int*   captions = (const int*)d_in[1];
    const int*   lengths  = (const int*)d_in[2];
    const float* emb      = (const float*)d_in[3];
    const float* h_fc_w   = (const float*)d_in[4];
    const float* h_fc_b   = (const float*)d_in[5];
    const float* c_fc_w   = (const float*)d_in[6];
    const float* c_fc_b   = (const float*)d_in[7];
    const float* enc_w    = (const float*)d_in[8];
    const float* enc_b    = (const float*)d_in[9];
    const float* dec_w    = (const float*)d_in[10];
    const float* dec_b    = (const float*)d_in[11];
    const float* att_w    = (const float*)d_in[12];
    const float* att_b    = (const float*)d_in[13];
    const float* beta_w   = (const float*)d_in[14];
    const float* beta_b   = (const float*)d_in[15];
    const float* w_ih     = (const float*)d_in[16];
    const float* b_ih     = (const float*)d_in[17];
    const float* w_hh     = (const float*)d_in[18];
    const float* b_hh     = (const float*)d_in[19];
    const float* cls_w    = (const float*)d_in[20];
    const float* cls_b    = (const float*)d_in[21];

    float* out = (float*)d_out;
    float* y_out = out;                               // (B, T, V)
    float* a_out = out + (size_t)Bc * Tc * Vc;        // (B, T, P)

    __half *feat16, *meanf16, *h16, *hn16, *att1_16, *eseq16;
    __half *hfcT, *cfcT, *encT, *abT, *w1T, *w2T, *clsT;
    float *cst, *egpre;
    cudaGetSymbolAddress((void**)&feat16,  g_feat16);
    cudaGetSymbolAddress((void**)&meanf16, g_meanf16);
    cudaGetSymbolAddress((void**)&h16,     g_h16);
    cudaGetSymbolAddress((void**)&hn16,    g_hn16);
    cudaGetSymbolAddress((void**)&att1_16, g_att1_16);
    cudaGetSymbolAddress((void**)&eseq16,  g_eseq16);
    cudaGetSymbolAddress((void**)&hfcT,    g_hfcT);
    cudaGetSymbolAddress((void**)&cfcT,    g_cfcT);
    cudaGetSymbolAddress((void**)&encT,    g_encT);
    cudaGetSymbolAddress((void**)&abT,     g_abT);
    cudaGetSymbolAddress((void**)&w1T,     g_w1T);
    cudaGetSymbolAddress((void**)&w2T,     g_w2T);
    cudaGetSymbolAddress((void**)&clsT,    g_clsT);
    cudaGetSymbolAddress((void**)&cst,     g_c);
    cudaGetSymbolAddress((void**)&egpre,   g_egpre);

    int smcount = 0, occ = 0;
    cudaDeviceGetAttribute(&smcount, cudaDevAttrMultiProcessorCount, 0);
    cudaOccupancyMaxActiveBlocksPerMultiprocessor(&occ, step_loop_kernel, 256, 0);
    if (occ < 1) occ = 1;
    if (occ > 2) occ = 2;
    int nb = smcount * occ;

    // ---- prologue --------------------------------------------------------
    f32to16_kernel<<<((Bc * Pc * Dc / 2) + 255) / 256, 256>>>(features, feat16, Bc * Pc * Dc / 2);
    transL(h_fc_w, hfcT, Dc, Hc, Dc, 0);
    transL(c_fc_w, cfcT, Dc, Hc, Dc, 0);
    transL(enc_w,  encT, Dc, Ac, Dc, 0);
    transL(dec_w,  abT, Hc, Ac, Hc, 0);                          // rows 0..511
    transL(beta_w, abT + (size_t)Ac * Hc, Hc, Dc, Hc, 0);        // rows 512..2559
    transL(w_hh,   abT + (size_t)NDB * Hc, Hc, G4H, Hc, 0);      // rows 2560..4607
    transL(w_ih,   w1T, Ec, G4H, Ec, 0);                         // w_ih rows 0..511
    transL(w_ih + (size_t)Ec * G4H, w2T, Dc, G4H, Dc, 0);        // w_ih rows 512..2559
    transL(cls_w,  clsT, Hc, Vc, Hc, 0);
    clspad_kernel<<<(((VPAD2 - Vc) * Hc) + 255) / 256, 256>>>();
    bias_prep_kernel<<<(NDB + 255) / 256, 256>>>(b_ih, b_hh, dec_b, beta_b);
    mean_kernel<<<(Bc * Dc + 255) / 256, 256>>>(features);
    embed_kernel<<<(Bc * Tc * Ec + 255) / 256, 256>>>(emb, captions);

    // h0 / c0 / att1 / egpre
    {
        dim3 g1(Hc / 64, Bc / 64);
        gemm_mma<64, 64><<<g1, 256>>>(meanf16, hfcT, h_fc_b, nullptr, h16, Bc, Hc, Dc, 0, Hc, 0, nullptr);
        gemm_mma<64, 64><<<g1, 256>>>(meanf16, cfcT, c_fc_b, cst, nullptr, Bc, Hc, Dc, Hc, 0, 0, nullptr);
        dim3 g2(Ac / 128, (Bc * Pc) / 64);
        gemm_mma<64, 128><<<g2, 256>>>(feat16, encT, enc_b, nullptr, att1_16, Bc * Pc, Ac, Dc, 0, Ac, 0, nullptr);
        // egpre = eseq @ W1  (M = B*Tc = 2432, N = 2048, K = 512)
        dim3 g4(G4H / 128, (Bc * Tc) / 64);
        gemm_mma<64, 128><<<g4, 256>>>(eseq16, w1T, nullptr, egpre, nullptr,
                                       Bc * Tc, G4H, Ec, G4H, 0, 0, nullptr);
    }

    // ---- persistent 19-step loop -----------------------------------------
    step_loop_kernel<<<nb, 256>>>(att_w, att_b, lengths, a_out);

    // ---- batched cls over all steps --------------------------------------
    {
        dim3 g3((Vc + 127) / 128, (Tc * Bc) / 64);
        gemm_mma<64, 128><<<g3, 256>>>(hn16, clsT, cls_b, y_out, nullptr,
                                       Tc * Bc, Vc, Hc, 0, 0, 3, lengths);
    }
}

// round 15
// speedup vs baseline: 1.0099x; 1.0099x over previous
#include <cuda_runtime.h>
#include <cuda_fp16.h>
#include <math.h>
#include <stdint.h>

// Problem constants
#define Bc 128
#define Pc 196
#define Dc 2048
#define Ac 512
#define Ec 512
#define Hc 512
#define Vc 10000
#define Tc 19
#define TMAXc 20
#define KCAT 3072   // E + D + H for fused gates GEMM
#define NDB 2560    // A + D for merged dec+beta GEMM
#define VPAD2 10112 // Vc padded to multiple of 128 (B-tile overread safety)
#define NSPL 4      // split-K for gates GEMM inside persistent kernel

// ---------------- scratch (device globals; no allocation allowed) ----------
__device__ __half g_feat16[(size_t)Bc * Pc * Dc];
__device__ __half g_meanf16[Bc * Dc];
__device__ __half g_h16[Bc * Hc];
__device__ float  g_c[Bc * Hc];
__device__ __half g_hn16[Tc][Bc * Hc];                // per-step hn for batched cls
__device__ __half g_att1_16[(size_t)Bc * Pc * Ac];
__device__ __half g_eseq16[(size_t)Bc * Tc * Ec];
__device__ float  g_att2[Bc * Ac];
__device__ float  g_alpha[Bc * Pc];
__device__ __half g_gate16[Bc * Dc];
__device__ __half g_xin16[Bc * KCAT];
__device__ float  g_gates[NSPL][Bc * 4 * Hc];
// transposed fp16 weights (K-major B operands: Bt[n][k])
__device__ __half g_hfcT[Hc * Dc];
__device__ __half g_cfcT[Hc * Dc];
__device__ __half g_encT[Ac * Dc];
__device__ __half g_dbT[(size_t)NDB * Hc];
__device__ float  g_dbbias[NDB];
__device__ __half g_wcatT[(size_t)(4 * Hc) * KCAT];
__device__ __half g_clsT[(size_t)VPAD2 * Hc];
__device__ float  g_bcat[4 * Hc];
// software grid barrier state
__device__ unsigned g_bar_count = 0;
__device__ unsigned g_bar_gen = 0;

// ---------------- helpers ---------------------------------------------------
__device__ __forceinline__ uint32_t smem_u32(const void* p) {
    uint32_t a;
    asm("{ .reg .u64 t; cvta.to.shared.u64 t, %1; cvt.u32.u64 %0, t; }" : "=r"(a) : "l"(p));
    return a;
}
__device__ __forceinline__ void cp16(uint32_t dst, const void* src) {
    asm volatile("cp.async.ca.shared.global [%0], [%1], 16;" :: "r"(dst), "l"(src));
}
#define CP_COMMIT() asm volatile("cp.async.commit_group;" ::: "memory")

__device__ __forceinline__ float sigf(float x) { return 1.f / (1.f + expf(-x)); }

__device__ __forceinline__ void grid_bar(unsigned nb) {
    __syncthreads();
    if (threadIdx.x == 0) {
        __threadfence();
        unsigned gen = atomicAdd(&g_bar_gen, 0u);
        unsigned prev = atomicAdd(&g_bar_count, 1u);
        if (prev == nb - 1) {
            atomicExch(&g_bar_count, 0u);
            __threadfence();
            atomicAdd(&g_bar_gen, 1u);
        } else {
            while (atomicAdd(&g_bar_gen, 0u) == gen) __nanosleep(64);
        }
        __threadfence();
    }
    __syncthreads();
}

#define ASTR 40
struct GemmSm { __half A[2][64 * ASTR]; __half B[2][64 * ASTR]; };   // 20480 B
struct AttSm  { float s2[Ac]; float sw[Ac]; float se[224]; float red[256]; };
union SmemU { GemmSm g; AttSm a; };

// 64x64 double-buffered mma core; all 256 threads participate.
__device__ __forceinline__ void gemm_core(SmemU& sm,
    const __half* __restrict__ Ab, const __half* __restrict__ Bb,
    int nk, int lda, int ldb, float acc[2][2][4])
{
    const int tid = threadIdx.x;
    const int lane = tid & 31, warp = tid >> 5;
    const int wm = warp >> 2, wn = warp & 3;
    const uint32_t sAu = smem_u32(sm.g.A);
    const uint32_t sBu = smem_u32(sm.g.B);
    const int aRow = wm * 32 + (lane & 15);
    const int aCol = (lane >= 16) ? 8 : 0;
    const int bRow = wn * 16 + (lane & 7);
    const int bCol = ((lane & 15) >= 8) ? 8 : 0;
    const int lr = tid >> 2, lq = tid & 3;

    #pragma unroll
    for (int i = 0; i < 2; i++)
        #pragma unroll
        for (int j = 0; j < 2; j++)
            #pragma unroll
            for (int e = 0; e < 4; e++) acc[i][j][e] = 0.f;

    cp16(sAu + (uint32_t)(lr * ASTR + lq * 8) * 2, Ab + (size_t)lr * lda + lq * 8);
    cp16(sBu + (uint32_t)(lr * ASTR + lq * 8) * 2, Bb + (size_t)lr * ldb + lq * 8);
    CP_COMMIT();

    for (int i = 0; i < nk; i++) {
        int buf = i & 1;
        if (i + 1 < nk) {
            int nbuf = buf ^ 1;
            int k0 = (i + 1) << 5;
            cp16(sAu + (uint32_t)(nbuf * 64 * ASTR + lr * ASTR + lq * 8) * 2,
                 Ab + (size_t)lr * lda + k0 + lq * 8);
            cp16(sBu + (uint32_t)(nbuf * 64 * ASTR + lr * ASTR + lq * 8) * 2,
                 Bb + (size_t)lr * ldb + k0 + lq * 8);
            CP_COMMIT();
            asm volatile("cp.async.wait_group 1;" ::: "memory");
        } else {
            asm volatile("cp.async.wait_group 0;" ::: "memory");
        }
        __syncthreads();
        uint32_t baseA = sAu + (uint32_t)(buf * 64 * ASTR) * 2;
        uint32_t baseB = sBu + (uint32_t)(buf * 64 * ASTR) * 2;
        #pragma unroll
        for (int ks = 0; ks < 32; ks += 16) {
            uint32_t a[2][4], b[2][2];
            #pragma unroll
            for (int mf = 0; mf < 2; mf++) {
                uint32_t addr = baseA + (uint32_t)((aRow + mf * 16) * ASTR + ks + aCol) * 2;
                asm volatile("ldmatrix.sync.aligned.m8n8.x4.shared.b16 {%0,%1,%2,%3}, [%4];"
                             : "=r"(a[mf][0]), "=r"(a[mf][1]), "=r"(a[mf][2]), "=r"(a[mf][3])
                             : "r"(addr));
            }
            #pragma unroll
            for (int nf = 0; nf < 2; nf++) {
                uint32_t addr = baseB + (uint32_t)((bRow + nf * 8) * ASTR + ks + bCol) * 2;
                asm volatile("ldmatrix.sync.aligned.m8n8.x2.shared.b16 {%0,%1}, [%2];"
                             : "=r"(b[nf][0]), "=r"(b[nf][1]) : "r"(addr));
            }
            #pragma unroll
            for (int mf = 0; mf < 2; mf++)
                #pragma unroll
                for (int nf = 0; nf < 2; nf++) {
                    float* cc = acc[mf][nf];
                    asm volatile(
                        "mma.sync.aligned.m16n8k16.row.col.f32.f16.f16.f32 "
                        "{%0,%1,%2,%3}, {%4,%5,%6,%7}, {%8,%9}, {%0,%1,%2,%3};"
                        : "+f"(cc[0]), "+f"(cc[1]), "+f"(cc[2]), "+f"(cc[3])
                        : "r"(a[mf][0]), "r"(a[mf][1]), "r"(a[mf][2]), "r"(a[mf][3]),
                          "r"(b[nf][0]), "r"(b[nf][1]));
                }
        }
        __syncthreads();
    }
}

// ---------------- persistent step-loop kernel --------------------------------
#define AWE8 (Bc * Dc / 8)
#define EC8  (Bc * Ec / 8)
#define HC8  (Bc * Hc / 8)
__device__ __forceinline__ void h2acc(uint32_t h2, float a, float& x, float& y) {
    float2 v = __half22float2(*(__half2*)&h2);
    x += a * v.x;
    y += a * v.y;
}

__global__ void __launch_bounds__(256, 2) step_loop_kernel(
    const float* __restrict__ att_w, const float* __restrict__ att_b,
    const int* __restrict__ lengths, float* __restrict__ a_out)
{
    __shared__ SmemU sm;
    const int tid = threadIdx.x;
    const int lane = tid & 31, warp = tid >> 5;
    const int wm = warp >> 2, wn = warp & 3;
    const unsigned nb = gridDim.x;
    const int gsize = (int)nb * 256;
    const int gid = blockIdx.x * 256 + tid;

    for (int t = 0; t < Tc; t++) {
        // ---- Phase A: [att2 | gate] = h @ dbT + dbbias (mode-2 routing) ----
        for (int u = blockIdx.x; u < 80; u += (int)nb) {
            int row0 = (u / 40) * 64, col0 = (u % 40) * 64;
            float acc[2][2][4];
            gemm_core(sm, g_h16 + (size_t)row0 * Hc, g_dbT + (size_t)col0 * Hc,
                      Hc >> 5, Hc, Hc, acc);
            int mbase = row0 + wm * 32, nbase = col0 + wn * 16;
            #pragma unroll
            for (int mf = 0; mf < 2; mf++)
                #pragma unroll
                for (int hr = 0; hr < 2; hr++) {
                    int m = mbase + mf * 16 + (lane >> 2) + hr * 8;
                    #pragma unroll
                    for (int nf = 0; nf < 2; nf++)
                        #pragma unroll
                        for (int e = 0; e < 2; e++) {
                            int n = nbase + nf * 8 + (lane & 3) * 2 + e;
                            float v = acc[mf][nf][hr * 2 + e] + g_dbbias[n];
                            if (n < Ac) g_att2[m * Ac + n] = v;
                            else g_gate16[m * Dc + (n - Ac)] = __float2half_rn(sigf(v));
                        }
                }
        }
        grid_bar(nb);

        // ---- Phase B: e = relu(att1 + att2) @ att_w + att_b; softmax ----
        for (int b = blockIdx.x; b < Bc; b += (int)nb) {
            for (int i = tid; i < Ac; i += 256) {
                sm.a.s2[i] = g_att2[b * Ac + i];
                sm.a.sw[i] = att_w[i];
            }
            __syncthreads();
            float attb = att_b[0];
            for (int p = warp; p < Pc; p += 8) {
                const __half2* a1 = (const __half2*)(g_att1_16 + ((size_t)b * Pc + p) * Ac);
                float s = 0.f;
                #pragma unroll
                for (int k = 0; k < 8; k++) {
                    int h2i = lane + 32 * k;
                    float2 v = __half22float2(a1[h2i]);
                    int a0 = 2 * h2i;
                    s += fmaxf(v.x + sm.a.s2[a0], 0.f) * sm.a.sw[a0];
                    s += fmaxf(v.y + sm.a.s2[a0 + 1], 0.f) * sm.a.sw[a0 + 1];
                }
                #pragma unroll
                for (int o = 16; o > 0; o >>= 1) s += __shfl_xor_sync(0xffffffffu, s, o);
                if (lane == 0) sm.a.se[p] = s + attb;
            }
            __syncthreads();
            float v = (tid < Pc) ? sm.a.se[tid] : -1e30f;
            sm.a.red[tid] = v;
            __syncthreads();
            for (int s = 128; s > 0; s >>= 1) {
                if (tid < s) sm.a.red[tid] = fmaxf(sm.a.red[tid], sm.a.red[tid + s]);
                __syncthreads();
            }
            float mx = sm.a.red[0];
            __syncthreads();
            float ex = (tid < Pc) ? expf(v - mx) : 0.f;
            sm.a.red[tid] = ex;
            __syncthreads();
            for (int s = 128; s > 0; s >>= 1) {
                if (tid < s) sm.a.red[tid] += sm.a.red[tid + s];
                __syncthreads();
            }
            float inv = 1.0f / sm.a.red[0];
            if (tid < Pc) {
                float al = ex * inv;
                g_alpha[b * Pc + tid] = al;
                float mf = (t < lengths[b] - 1) ? 1.f : 0.f;
                a_out[((size_t)b * Tc + t) * Pc + tid] = al * mf;
            }
            __syncthreads();
        }
        grid_bar(nb);

        // ---- Phase C: xin = [e_t | gate * (alpha @ features) | h] ----
        for (int idx = gid; idx < AWE8 + EC8 + HC8; idx += gsize) {
            uint4* xin4 = (uint4*)g_xin16;
            if (idx < AWE8) {
                int b = idx / (Dc / 8), d8 = idx % (Dc / 8);
                const uint4* fp = ((const uint4*)g_feat16) + (size_t)b * Pc * (Dc / 8) + d8;
                const float* al = g_alpha + b * Pc;
                float s[8] = {0.f, 0.f, 0.f, 0.f, 0.f, 0.f, 0.f, 0.f};
                #pragma unroll 4
                for (int p = 0; p < Pc; p++) {
                    float a = al[p];
                    uint4 v = fp[(size_t)p * (Dc / 8)];
                    h2acc(v.x, a, s[0], s[1]);
                    h2acc(v.y, a, s[2], s[3]);
                    h2acc(v.z, a, s[4], s[5]);
                    h2acc(v.w, a, s[6], s[7]);
                }
                uint4 g4 = ((const uint4*)g_gate16)[b * (Dc / 8) + d8];
                float2 g0 = __half22float2(*(__half2*)&g4.x);
                float2 g1 = __half22float2(*(__half2*)&g4.y);
                float2 g2 = __half22float2(*(__half2*)&g4.z);
                float2 g3 = __half22float2(*(__half2*)&g4.w);
                __half2 r0 = __floats2half2_rn(s[0] * g0.x, s[1] * g0.y);
                __half2 r1 = __floats2half2_rn(s[2] * g1.x, s[3] * g1.y);
                __half2 r2 = __floats2half2_rn(s[4] * g2.x, s[5] * g2.y);
                __half2 r3 = __floats2half2_rn(s[6] * g3.x, s[7] * g3.y);
                uint4 r;
                r.x = *(uint32_t*)&r0; r.y = *(uint32_t*)&r1;
                r.z = *(uint32_t*)&r2; r.w = *(uint32_t*)&r3;
                xin4[b * (KCAT / 8) + (Ec / 8) + d8] = r;
            } else if (idx < AWE8 + EC8) {
                int i = idx - AWE8;
                int b = i / (Ec / 8), j = i % (Ec / 8);
                xin4[b * (KCAT / 8) + j] =
                    ((const uint4*)g_eseq16)[((size_t)b * Tc + t) * (Ec / 8) + j];
            } else {
                int i = idx - AWE8 - EC8;
                int b = i / (Hc / 8), j = i % (Hc / 8);
                xin4[b * (KCAT / 8) + ((Ec + Dc) / 8) + j] =
                    ((const uint4*)g_h16)[b * (Hc / 8) + j];
            }
        }
        grid_bar(nb);

        // ---- Phase D: gates partials = xin @ wcatT (split-K=4) ----
        for (int u = blockIdx.x; u < 2 * 32 * NSPL; u += (int)nb) {
            int z = u & (NSPL - 1), uu = u >> 2;
            int row0 = (uu / 32) * 64, col0 = (uu % 32) * 64;
            float acc[2][2][4];
            gemm_core(sm, g_xin16 + (size_t)row0 * KCAT + z * (KCAT / NSPL),
                      g_wcatT + (size_t)col0 * KCAT + z * (KCAT / NSPL),
                      (KCAT / NSPL) >> 5, KCAT, KCAT, acc);
            int mbase = row0 + wm * 32, nbase = col0 + wn * 16;
            float* gz = g_gates[z];
            #pragma unroll
            for (int mf = 0; mf < 2; mf++)
                #pragma unroll
                for (int hr = 0; hr < 2; hr++) {
                    int m = mbase + mf * 16 + (lane >> 2) + hr * 8;
                    #pragma unroll
                    for (int nf = 0; nf < 2; nf++)
                        #pragma unroll
                        for (int e = 0; e < 2; e++) {
                            int n = nbase + nf * 8 + (lane & 3) * 2 + e;
                            gz[(size_t)m * (4 * Hc) + n] = acc[mf][nf][hr * 2 + e];
                        }
                }
        }
        grid_bar(nb);

        // ---- Phase E: LSTM pointwise ----
        for (int idx = gid; idx < Bc * Hc; idx += gsize) {
            int b = idx / Hc, j = idx % Hc;
            size_t base = (size_t)b * 4 * Hc;
            float i_ = g_bcat[j],          f_ = g_bcat[Hc + j];
            float gg = g_bcat[2 * Hc + j], o_ = g_bcat[3 * Hc + j];
            #pragma unroll
            for (int z = 0; z < NSPL; z++) {
                const float* gr = g_gates[z] + base;
                i_ += gr[j];
                f_ += gr[Hc + j];
                gg += gr[2 * Hc + j];
                o_ += gr[3 * Hc + j];
            }
            float cn = sigf(f_) * g_c[idx] + sigf(i_) * tanhf(gg);
            float hn = sigf(o_) * tanhf(cn);
            g_hn16[t][idx] = __float2half_rn(hn);
            if (t < lengths[b] - 1) {
                g_h16[idx] = __float2half_rn(hn);
                g_c[idx] = cn;
            }
        }
        grid_bar(nb);
    }
}

// ---------------- template GEMM for prologue + batched cls -------------------
// mode 0: plain bias (+C/C16). mode 3: batched cls (row m -> t=m>>7, b=m&127).
template<int BM, int BN>
__global__ void __launch_bounds__(256) gemm_mma(
    const __half* __restrict__ A, const __half* __restrict__ Bt,
    const float* __restrict__ bias, float* __restrict__ C, __half* __restrict__ C16,
    int M, int N, int K, int ldc, int ld16, int mode,
    const int* __restrict__ lengths)
{
    constexpr int MFRAG = BM / 32;
    constexpr int NFRAG = BN / 32;
    __shared__ __half sA[2][BM * ASTR];
    __shared__ __half sB[2][BN * ASTR];

    const int tid = threadIdx.x;
    const int lane = tid & 31, warp = tid >> 5;
    const int wm = warp >> 2, wn = warp & 3;
    const int row0 = blockIdx.y * BM, col0 = blockIdx.x * BN;

    const __half* Ab = A + (size_t)row0 * K;
    const __half* Bb = Bt + (size_t)col0 * K;
    const int nk = K >> 5;

    const uint32_t sAu = smem_u32(sA);
    const uint32_t sBu = smem_u32(sB);

    float acc[MFRAG][NFRAG][4];
    #pragma unroll
    for (int i = 0; i < MFRAG; i++)
        #pragma unroll
        for (int j = 0; j < NFRAG; j++)
            #pragma unroll
            for (int e = 0; e < 4; e++) acc[i][j][e] = 0.f;

    const int aRow = wm * (BM / 2) + (lane & 15);
    const int aCol = (lane >= 16) ? 8 : 0;
    const int bRow = wn * (BN / 4) + (lane & 7);
    const int bCol = ((lane & 15) >= 8) ? 8 : 0;

    {
        #pragma unroll
        for (int l = 0; l < BM / 64; l++) {
            int c = tid + l * 256;
            int r = c >> 2, q = c & 3;
            cp16(sAu + (uint32_t)(r * ASTR + q * 8) * 2, Ab + (size_t)r * K + q * 8);
        }
        #pragma unroll
        for (int l = 0; l < BN / 64; l++) {
            int c = tid + l * 256;
            int r = c >> 2, q = c & 3;
            cp16(sBu + (uint32_t)(r * ASTR + q * 8) * 2, Bb + (size_t)r * K + q * 8);
        }
    }
    CP_COMMIT();

    for (int i = 0; i < nk; i++) {
        int buf = i & 1;
        if (i + 1 < nk) {
            int nbuf = buf ^ 1;
            int k0 = (i + 1) << 5;
            #pragma unroll
            for (int l = 0; l < BM / 64; l++) {
                int c = tid + l * 256;
                int r = c >> 2, q = c & 3;
                cp16(sAu + (uint32_t)(nbuf * BM * ASTR + r * ASTR + q * 8) * 2,
                     Ab + (size_t)r * K + k0 + q * 8);
            }
            #pragma unroll
            for (int l = 0; l < BN / 64; l++) {
                int c = tid + l * 256;
                int r = c >> 2, q = c & 3;
                cp16(sBu + (uint32_t)(nbuf * BN * ASTR + r * ASTR + q * 8) * 2,
                     Bb + (size_t)r * K + k0 + q * 8);
            }
            CP_COMMIT();
            asm volatile("cp.async.wait_group 1;" ::: "memory");
        } else {
            asm volatile("cp.async.wait_group 0;" ::: "memory");
        }
        __syncthreads();

        uint32_t baseA = sAu + (uint32_t)(buf * BM * ASTR) * 2;
        uint32_t baseB = sBu + (uint32_t)(buf * BN * ASTR) * 2;
        #pragma unroll
        for (int ks = 0; ks < 32; ks += 16) {
            uint32_t a[MFRAG][4], b[NFRAG][2];
            #pragma unroll
            for (int mf = 0; mf < MFRAG; mf++) {
                uint32_t addr = baseA + (uint32_t)((aRow + mf * 16) * ASTR + ks + aCol) * 2;
                asm volatile("ldmatrix.sync.aligned.m8n8.x4.shared.b16 {%0,%1,%2,%3}, [%4];"
                             : "=r"(a[mf][0]), "=r"(a[mf][1]), "=r"(a[mf][2]), "=r"(a[mf][3])
                             : "r"(addr));
            }
            #pragma unroll
            for (int nf = 0; nf < NFRAG; nf++) {
                uint32_t addr = baseB + (uint32_t)((bRow + nf * 8) * ASTR + ks + bCol) * 2;
                asm volatile("ldmatrix.sync.aligned.m8n8.x2.shared.b16 {%0,%1}, [%2];"
                             : "=r"(b[nf][0]), "=r"(b[nf][1]) : "r"(addr));
            }
            #pragma unroll
            for (int mf = 0; mf < MFRAG; mf++)
                #pragma unroll
                for (int nf = 0; nf < NFRAG; nf++) {
                    float* cc = acc[mf][nf];
                    asm volatile(
                        "mma.sync.aligned.m16n8k16.row.col.f32.f16.f16.f32 "
                        "{%0,%1,%2,%3}, {%4,%5,%6,%7}, {%8,%9}, {%0,%1,%2,%3};"
                        : "+f"(cc[0]), "+f"(cc[1]), "+f"(cc[2]), "+f"(cc[3])
                        : "r"(a[mf][0]), "r"(a[mf][1]), "r"(a[mf][2]), "r"(a[mf][3]),
                          "r"(b[nf][0]), "r"(b[nf][1]));
                }
        }
        __syncthreads();
    }

    const int mbase = row0 + wm * (BM / 2);
    const int nbase = col0 + wn * (BN / 4);
    #pragma unroll
    for (int mf = 0; mf < MFRAG; mf++) {
        #pragma unroll
        for (int hr = 0; hr < 2; hr++) {
            int m = mbase + mf * 16 + (lane >> 2) + hr * 8;
            #pragma unroll
            for (int nf = 0; nf < NFRAG; nf++) {
                #pragma unroll
                for (int e = 0; e < 2; e++) {
                    int n = nbase + nf * 8 + (lane & 3) * 2 + e;
                    if (n < N) {
                        float v = acc[mf][nf][hr * 2 + e];
                        if (bias) v += bias[n];
                        if (mode == 3) {
                            int tt = m >> 7, bb = m & 127;
                            float mk = (tt < lengths[bb] - 1) ? 1.f : 0.f;
                            C[((size_t)bb * Tc + tt) * Vc + n] = v * mk;
                        } else {
                            if (C)   C[(size_t)m * ldc + n] = v;
                            if (C16) C16[(size_t)m * ld16 + n] = __float2half_rn(v);
                        }
                    }
                }
            }
        }
    }
}

// ---------------- support kernels -------------------------------------------

__global__ void f32to16_kernel(const float* __restrict__ in, __half* __restrict__ out, int n2) {
    int i = blockIdx.x * blockDim.x + threadIdx.x;
    if (i < n2) {
        float2 v = ((const float2*)in)[i];
        ((__half2*)out)[i] = __floats2half2_rn(v.x, v.y);
    }
}

__global__ void transpose16_kernel(const float* __restrict__ in, __half* __restrict__ out,
                                   int K, int N, int out_ld, int k_off) {
    __shared__ float tile[32][33];
    int kb = blockIdx.y * 32, nb = blockIdx.x * 32;
    int x = threadIdx.x, y = threadIdx.y;
    #pragma unroll
    for (int j = 0; j < 32; j += 8) {
        int k = kb + y + j, n = nb + x;
        tile[y + j][x] = (k < K && n < N) ? in[(size_t)k * N + n] : 0.f;
    }
    __syncthreads();
    #pragma unroll
    for (int j = 0; j < 32; j += 8) {
        int n = nb + y + j, k = kb + x;
        if (n < N && k < K) out[(size_t)n * out_ld + k_off + k] = __float2half_rn(tile[x][y + j]);
    }
}

__global__ void clspad_kernel() {
    int i = blockIdx.x * blockDim.x + threadIdx.x;
    int total = (VPAD2 - Vc) * Hc;
    if (i < total) g_clsT[(size_t)Vc * Hc + i] = __float2half_rn(0.f);
}

__global__ void bias_prep_kernel(const float* __restrict__ bi, const float* __restrict__ bh,
                                 const float* __restrict__ db, const float* __restrict__ bb) {
    int i = blockIdx.x * blockDim.x + threadIdx.x;
    if (i < 4 * Hc) g_bcat[i] = bi[i] + bh[i];
    if (i < NDB) g_dbbias[i] = (i < Ac) ? db[i] : bb[i - Ac];
}

__global__ void mean_kernel(const float* __restrict__ f) {
    int idx = blockIdx.x * blockDim.x + threadIdx.x;
    if (idx >= Bc * Dc) return;
    int b = idx / Dc, d = idx % Dc;
    const float* p = f + (size_t)b * Pc * Dc + d;
    float s = 0.f;
    #pragma unroll 4
    for (int i = 0; i < Pc; i++) s += p[(size_t)i * Dc];
    g_meanf16[idx] = __float2half_rn(s * (1.0f / Pc));
}

__global__ void embed_kernel(const float* __restrict__ emb, const int* __restrict__ cap) {
    int idx = blockIdx.x * blockDim.x + threadIdx.x;
    if (idx >= Bc * Tc * Ec) return;
    int j = idx % Ec;
    int bt = idx / Ec;
    int t = bt % Tc;
    int b = bt / Tc;
    int tok = cap[b * TMAXc + t];
    g_eseq16[idx] = __float2half_rn(emb[(size_t)tok * Ec + j]);
}

// ---------------- launcher ---------------------------------------------------

static void transL(const float* in, __half* out, int K, int N, int out_ld, int k_off) {
    dim3 grid((N + 31) / 32, (K + 31) / 32);
    transpose16_kernel<<<grid, dim3(32, 8)>>>(in, out, K, N, out_ld, k_off);
}

extern "C" void kernel_launch(void* const* d_in, const int* in_sizes, int n_in,
                              void* d_out, int out_size) {
    const float* features = (const float*)d_in[0];
    const int*   captions = (const int*)d_in[1];
    const int*   lengths  = (const int*)d_in[2];
    const float* emb      = (const float*)d_in[3];
    const float* h_fc_w   = (const float*)d_in[4];
    const float* h_fc_b   = (const float*)d_in[5];
    const float* c_fc_w   = (const float*)d_in[6];
    const float* c_fc_b   = (const float*)d_in[7];
    const float* enc_w    = (const float*)d_in[8];
    const float* enc_b    = (const float*)d_in[9];
    const float* dec_w    = (const float*)d_in[10];
    const float* dec_b    = (const float*)d_in[11];
    const float* att_w    = (const float*)d_in[12];
    const float* att_b    = (const float*)d_in[13];
    const float* beta_w   = (const float*)d_in[14];
    const float* beta_b   = (const float*)d_in[15];
    const float* w_ih     = (const float*)d_in[16];
    const float* b_ih     = (const float*)d_in[17];
    const float* w_hh     = (const float*)d_in[18];
    const float* b_hh     = (const float*)d_in[19];
    const float* cls_w    = (const float*)d_in[20];
    const float* cls_b    = (const float*)d_in[21];

    float* out = (float*)d_out;
    float* y_out = out;                               // (B, T, V)
    float* a_out = out + (size_t)Bc * Tc * Vc;        // (B, T, P)

    __half *feat16, *meanf16, *h16, *hn16, *att1_16;
    __half *hfcT, *cfcT, *encT, *dbT, *wcatT, *clsT;
    float *cst;
    cudaGetSymbolAddress((void**)&feat16,  g_feat16);
    cudaGetSymbolAddress((void**)&meanf16, g_meanf16);
    cudaGetSymbolAddress((void**)&h16,     g_h16);
    cudaGetSymbolAddress((void**)&hn16,    g_hn16);
    cudaGetSymbolAddress((void**)&att1_16, g_att1_16);
    cudaGetSymbolAddress((void**)&hfcT,    g_hfcT);
    cudaGetSymbolAddress((void**)&cfcT,    g_cfcT);
    cudaGetSymbolAddress((void**)&encT,    g_encT);
    cudaGetSymbolAddress((void**)&dbT,     g_dbT);
    cudaGetSymbolAddress((void**)&wcatT,   g_wcatT);
    cudaGetSymbolAddress((void**)&clsT,    g_clsT);
    cudaGetSymbolAddress((void**)&cst,     g_c);

    // persistent-kernel grid: 128 blocks (>= all phase unit counts that matter,
    // minimizes same-address atomic serialization in the grid barrier).
    int smcount = 0, occ = 0;
    cudaDeviceGetAttribute(&smcount, cudaDevAttrMultiProcessorCount, 0);
    cudaOccupancyMaxActiveBlocksPerMultiprocessor(&occ, step_loop_kernel, 256, 0);
    if (occ < 1) occ = 1;
    int nb = 128;
    if (smcount * occ < nb) nb = smcount * occ;

    // ---- prologue --------------------------------------------------------
    f32to16_kernel<<<((Bc * Pc * Dc / 2) + 255) / 256, 256>>>(features, feat16, Bc * Pc * Dc / 2);
    transL(h_fc_w, hfcT, Dc, Hc, Dc, 0);
    transL(c_fc_w, cfcT, Dc, Hc, Dc, 0);
    transL(enc_w,  encT, Dc, Ac, Dc, 0);
    transL(dec_w,  dbT, Hc, Ac, Hc, 0);
    transL(beta_w, dbT + (size_t)Ac * Hc, Hc, Dc, Hc, 0);
    transL(w_ih,   wcatT, Dc + Ec, 4 * Hc, KCAT, 0);
    transL(w_hh,   wcatT, Hc, 4 * Hc, KCAT, Dc + Ec);
    transL(cls_w,  clsT, Hc, Vc, Hc, 0);
    clspad_kernel<<<(((VPAD2 - Vc) * Hc) + 255) / 256, 256>>>();
    bias_prep_kernel<<<(NDB + 255) / 256, 256>>>(b_ih, b_hh, dec_b, beta_b);
    mean_kernel<<<(Bc * Dc + 255) / 256, 256>>>(features);
    embed_kernel<<<(Bc * Tc * Ec + 255) / 256, 256>>>(emb, captions);

    // h0 / c0 / att1
    {
        dim3 g1(Hc / 64, Bc / 64);
        gemm_mma<64, 64><<<g1, 256>>>(meanf16, hfcT, h_fc_b, nullptr, h16, Bc, Hc, Dc, 0, Hc, 0, nullptr);
        gemm_mma<64, 64><<<g1, 256>>>(meanf16, cfcT, c_fc_b, cst, nullptr, Bc, Hc, Dc, Hc, 0, 0, nullptr);
        dim3 g2(Ac / 128, (Bc * Pc) / 64);
        gemm_mma<64, 128><<<g2, 256>>>(feat16, encT, enc_b, nullptr, att1_16, Bc * Pc, Ac, Dc, 0, Ac, 0, nullptr);
    }

    // ---- persistent 19-step loop -----------------------------------------
    step_loop_kernel<<<nb, 256>>>(att_w, att_b, lengths, a_out);

    // ---- batched cls over all steps: (Tc*Bc, Vc) = hn_all @ clsT ---------
    {
        dim3 g3((Vc + 127) / 128, (Tc * Bc) / 64);
        gemm_mma<64, 128><<<g3, 256>>>(hn16, clsT, cls_b, y_out, nullptr,
                                       Tc * Bc, Vc, Hc, 0, 0, 3, lengths);
    }
}

// round 16
// speedup vs baseline: 1.1745x; 1.1629x over previous
#include <cuda_runtime.h>
#include <cuda_fp16.h>
#include <math.h>
#include <stdint.h>

// Problem constants
#define Bc 128
#define Pc 196
#define Dc 2048
#define Ac 512
#define Ec 512
#define Hc 512
#define Vc 10000
#define Tc 19
#define TMAXc 20
#define KCAT 3072   // E + D + H for fused gates GEMM
#define NDB 2560    // A + D for merged dec+beta GEMM
#define VPAD2 10112 // Vc padded to multiple of 128 (B-tile overread safety)
#define NSPL 4      // split-K for gates GEMM inside persistent kernel

// ---------------- scratch (device globals; no allocation allowed) ----------
__device__ __half g_feat16[(size_t)Bc * Pc * Dc];
__device__ __half g_meanf16[Bc * Dc];
__device__ __half g_h16[Bc * Hc];
__device__ float  g_c[Bc * Hc];
__device__ __half g_hn16[Tc][Bc * Hc];                // per-step hn for batched cls
__device__ __half g_att1_16[(size_t)Bc * Pc * Ac];
__device__ __half g_eseq16[(size_t)Bc * Tc * Ec];
__device__ float  g_att2[Bc * Ac];
__device__ float  g_alpha[Bc * Pc];
__device__ __half g_gate16[Bc * Dc];
__device__ __half g_xin16[Bc * KCAT];
__device__ float  g_gates[NSPL][Bc * 4 * Hc];
// transposed fp16 weights (K-major B operands: Bt[n][k])
__device__ __half g_hfcT[Hc * Dc];
__device__ __half g_cfcT[Hc * Dc];
__device__ __half g_encT[Ac * Dc];
__device__ __half g_dbT[(size_t)NDB * Hc];
__device__ float  g_dbbias[NDB];
__device__ __half g_wcatT[(size_t)(4 * Hc) * KCAT];
__device__ __half g_clsT[(size_t)VPAD2 * Hc];
__device__ float  g_bcat[4 * Hc];
// software grid barrier state
__device__ unsigned g_bar_count = 0;
__device__ unsigned g_bar_gen = 0;

// ---------------- helpers ---------------------------------------------------
__device__ __forceinline__ uint32_t smem_u32(const void* p) {
    uint32_t a;
    asm("{ .reg .u64 t; cvta.to.shared.u64 t, %1; cvt.u32.u64 %0, t; }" : "=r"(a) : "l"(p));
    return a;
}
__device__ __forceinline__ void cp16(uint32_t dst, const void* src) {
    asm volatile("cp.async.ca.shared.global [%0], [%1], 16;" :: "r"(dst), "l"(src));
}
#define CP_COMMIT() asm volatile("cp.async.commit_group;" ::: "memory")

__device__ __forceinline__ float sigf(float x) { return 1.f / (1.f + expf(-x)); }

__device__ __forceinline__ void grid_bar(unsigned nb) {
    __syncthreads();
    if (threadIdx.x == 0) {
        __threadfence();
        unsigned gen = atomicAdd(&g_bar_gen, 0u);
        unsigned prev = atomicAdd(&g_bar_count, 1u);
        if (prev == nb - 1) {
            atomicExch(&g_bar_count, 0u);
            __threadfence();
            atomicAdd(&g_bar_gen, 1u);
        } else {
            while (atomicAdd(&g_bar_gen, 0u) == gen) __nanosleep(64);
        }
        __threadfence();
    }
    __syncthreads();
}

#define ASTR 40
struct GemmSm { __half A[2][64 * ASTR]; __half B[2][64 * ASTR]; };   // 20480 B
struct AttSm  { float s2[Ac]; float sw[Ac]; float se[224]; float red[256]; };
union SmemU { GemmSm g; AttSm a; };

// 64x64 double-buffered mma core; all 256 threads participate.
__device__ __forceinline__ void gemm_core(SmemU& sm,
    const __half* __restrict__ Ab, const __half* __restrict__ Bb,
    int nk, int lda, int ldb, float acc[2][2][4])
{
    const int tid = threadIdx.x;
    const int lane = tid & 31, warp = tid >> 5;
    const int wm = warp >> 2, wn = warp & 3;
    const uint32_t sAu = smem_u32(sm.g.A);
    const uint32_t sBu = smem_u32(sm.g.B);
    const int aRow = wm * 32 + (lane & 15);
    const int aCol = (lane >= 16) ? 8 : 0;
    const int bRow = wn * 16 + (lane & 7);
    const int bCol = ((lane & 15) >= 8) ? 8 : 0;
    const int lr = tid >> 2, lq = tid & 3;

    #pragma unroll
    for (int i = 0; i < 2; i++)
        #pragma unroll
        for (int j = 0; j < 2; j++)
            #pragma unroll
            for (int e = 0; e < 4; e++) acc[i][j][e] = 0.f;

    cp16(sAu + (uint32_t)(lr * ASTR + lq * 8) * 2, Ab + (size_t)lr * lda + lq * 8);
    cp16(sBu + (uint32_t)(lr * ASTR + lq * 8) * 2, Bb + (size_t)lr * ldb + lq * 8);
    CP_COMMIT();

    for (int i = 0; i < nk; i++) {
        int buf = i & 1;
        if (i + 1 < nk) {
            int nbuf = buf ^ 1;
            int k0 = (i + 1) << 5;
            cp16(sAu + (uint32_t)(nbuf * 64 * ASTR + lr * ASTR + lq * 8) * 2,
                 Ab + (size_t)lr * lda + k0 + lq * 8);
            cp16(sBu + (uint32_t)(nbuf * 64 * ASTR + lr * ASTR + lq * 8) * 2,
                 Bb + (size_t)lr * ldb + k0 + lq * 8);
            CP_COMMIT();
            asm volatile("cp.async.wait_group 1;" ::: "memory");
        } else {
            asm volatile("cp.async.wait_group 0;" ::: "memory");
        }
        __syncthreads();
        uint32_t baseA = sAu + (uint32_t)(buf * 64 * ASTR) * 2;
        uint32_t baseB = sBu + (uint32_t)(buf * 64 * ASTR) * 2;
        #pragma unroll
        for (int ks = 0; ks < 32; ks += 16) {
            uint32_t a[2][4], b[2][2];
            #pragma unroll
            for (int mf = 0; mf < 2; mf++) {
                uint32_t addr = baseA + (uint32_t)((aRow + mf * 16) * ASTR + ks + aCol) * 2;
                asm volatile("ldmatrix.sync.aligned.m8n8.x4.shared.b16 {%0,%1,%2,%3}, [%4];"
                             : "=r"(a[mf][0]), "=r"(a[mf][1]), "=r"(a[mf][2]), "=r"(a[mf][3])
                             : "r"(addr));
            }
            #pragma unroll
            for (int nf = 0; nf < 2; nf++) {
                uint32_t addr = baseB + (uint32_t)((bRow + nf * 8) * ASTR + ks + bCol) * 2;
                asm volatile("ldmatrix.sync.aligned.m8n8.x2.shared.b16 {%0,%1}, [%2];"
                             : "=r"(b[nf][0]), "=r"(b[nf][1]) : "r"(addr));
            }
            #pragma unroll
            for (int mf = 0; mf < 2; mf++)
                #pragma unroll
                for (int nf = 0; nf < 2; nf++) {
                    float* cc = acc[mf][nf];
                    asm volatile(
                        "mma.sync.aligned.m16n8k16.row.col.f32.f16.f16.f32 "
                        "{%0,%1,%2,%3}, {%4,%5,%6,%7}, {%8,%9}, {%0,%1,%2,%3};"
                        : "+f"(cc[0]), "+f"(cc[1]), "+f"(cc[2]), "+f"(cc[3])
                        : "r"(a[mf][0]), "r"(a[mf][1]), "r"(a[mf][2]), "r"(a[mf][3]),
                          "r"(b[nf][0]), "r"(b[nf][1]));
                }
        }
        __syncthreads();
    }
}

// ---------------- persistent step-loop kernel --------------------------------
#define AWEH (Bc * Dc / 4)   // 65536 half-column work items (2 per (b,d8))
#define EC8  (Bc * Ec / 8)
#define HC8  (Bc * Hc / 8)
__device__ __forceinline__ void h2acc(uint32_t h2, float a, float& x, float& y) {
    float2 v = __half22float2(*(__half2*)&h2);
    x += a * v.x;
    y += a * v.y;
}

__global__ void __launch_bounds__(256, 2) step_loop_kernel(
    const float* __restrict__ att_w, const float* __restrict__ att_b,
    const int* __restrict__ lengths, float* __restrict__ a_out)
{
    __shared__ SmemU sm;
    const int tid = threadIdx.x;
    const int lane = tid & 31, warp = tid >> 5;
    const int wm = warp >> 2, wn = warp & 3;
    const unsigned nb = gridDim.x;
    const int gsize = (int)nb * 256;
    const int gid = blockIdx.x * 256 + tid;

    for (int t = 0; t < Tc; t++) {
        // ---- Phase A: [att2 | gate] = h @ dbT + dbbias (mode-2 routing) ----
        for (int u = blockIdx.x; u < 80; u += (int)nb) {
            int row0 = (u / 40) * 64, col0 = (u % 40) * 64;
            float acc[2][2][4];
            gemm_core(sm, g_h16 + (size_t)row0 * Hc, g_dbT + (size_t)col0 * Hc,
                      Hc >> 5, Hc, Hc, acc);
            int mbase = row0 + wm * 32, nbase = col0 + wn * 16;
            #pragma unroll
            for (int mf = 0; mf < 2; mf++)
                #pragma unroll
                for (int hr = 0; hr < 2; hr++) {
                    int m = mbase + mf * 16 + (lane >> 2) + hr * 8;
                    #pragma unroll
                    for (int nf = 0; nf < 2; nf++)
                        #pragma unroll
                        for (int e = 0; e < 2; e++) {
                            int n = nbase + nf * 8 + (lane & 3) * 2 + e;
                            float v = acc[mf][nf][hr * 2 + e] + g_dbbias[n];
                            if (n < Ac) g_att2[m * Ac + n] = v;
                            else g_gate16[m * Dc + (n - Ac)] = __float2half_rn(sigf(v));
                        }
                }
        }
        grid_bar(nb);

        // ---- Phase B: e = relu(att1 + att2) @ att_w + att_b; softmax ----
        for (int b = blockIdx.x; b < Bc; b += (int)nb) {
            for (int i = tid; i < Ac; i += 256) {
                sm.a.s2[i] = g_att2[b * Ac + i];
                sm.a.sw[i] = att_w[i];
            }
            __syncthreads();
            float attb = att_b[0];
            for (int p = warp; p < Pc; p += 8) {
                const __half2* a1 = (const __half2*)(g_att1_16 + ((size_t)b * Pc + p) * Ac);
                float s = 0.f;
                #pragma unroll
                for (int k = 0; k < 8; k++) {
                    int h2i = lane + 32 * k;
                    float2 v = __half22float2(a1[h2i]);
                    int a0 = 2 * h2i;
                    s += fmaxf(v.x + sm.a.s2[a0], 0.f) * sm.a.sw[a0];
                    s += fmaxf(v.y + sm.a.s2[a0 + 1], 0.f) * sm.a.sw[a0 + 1];
                }
                #pragma unroll
                for (int o = 16; o > 0; o >>= 1) s += __shfl_xor_sync(0xffffffffu, s, o);
                if (lane == 0) sm.a.se[p] = s + attb;
            }
            __syncthreads();
            float v = (tid < Pc) ? sm.a.se[tid] : -1e30f;
            sm.a.red[tid] = v;
            __syncthreads();
            for (int s = 128; s > 0; s >>= 1) {
                if (tid < s) sm.a.red[tid] = fmaxf(sm.a.red[tid], sm.a.red[tid + s]);
                __syncthreads();
            }
            float mx = sm.a.red[0];
            __syncthreads();
            float ex = (tid < Pc) ? expf(v - mx) : 0.f;
            sm.a.red[tid] = ex;
            __syncthreads();
            for (int s = 128; s > 0; s >>= 1) {
                if (tid < s) sm.a.red[tid] += sm.a.red[tid + s];
                __syncthreads();
            }
            float inv = 1.0f / sm.a.red[0];
            if (tid < Pc) {
                float al = ex * inv;
                g_alpha[b * Pc + tid] = al;
                float mf = (t < lengths[b] - 1) ? 1.f : 0.f;
                a_out[((size_t)b * Tc + t) * Pc + tid] = al * mf;
            }
            __syncthreads();
        }
        grid_bar(nb);

        // ---- Phase C: xin = [e_t | gate * (alpha @ features) | h] ----
        // awe computed by lane-pairs: even lane sums p in [0,98), odd lane
        // [98,196); combined via shfl. Region boundaries are multiples of 32
        // and gsize is warp-aligned, so no warp straddles a branch.
        for (int idx = gid; idx < AWEH + EC8 + HC8; idx += gsize) {
            uint4* xin4 = (uint4*)g_xin16;
            if (idx < AWEH) {
                int half = idx & 1;
                int pair = idx >> 1;
                int b = pair / (Dc / 8), d8 = pair % (Dc / 8);
                const uint4* fp = ((const uint4*)g_feat16)
                    + (size_t)b * Pc * (Dc / 8) + (size_t)(half * 98) * (Dc / 8) + d8;
                const float* al = g_alpha + b * Pc + half * 98;
                float s[8] = {0.f, 0.f, 0.f, 0.f, 0.f, 0.f, 0.f, 0.f};
                #pragma unroll 4
                for (int p = 0; p < 98; p++) {
                    float a = al[p];
                    uint4 v = fp[(size_t)p * (Dc / 8)];
                    h2acc(v.x, a, s[0], s[1]);
                    h2acc(v.y, a, s[2], s[3]);
                    h2acc(v.z, a, s[4], s[5]);
                    h2acc(v.w, a, s[6], s[7]);
                }
                #pragma unroll
                for (int k = 0; k < 8; k++) {
                    float o = __shfl_down_sync(0xffffffffu, s[k], 1);
                    s[k] += o;
                }
                if (!half) {
                    uint4 g4 = ((const uint4*)g_gate16)[b * (Dc / 8) + d8];
                    float2 g0 = __half22float2(*(__half2*)&g4.x);
                    float2 g1 = __half22float2(*(__half2*)&g4.y);
                    float2 g2 = __half22float2(*(__half2*)&g4.z);
                    float2 g3 = __half22float2(*(__half2*)&g4.w);
                    __half2 r0 = __floats2half2_rn(s[0] * g0.x, s[1] * g0.y);
                    __half2 r1 = __floats2half2_rn(s[2] * g1.x, s[3] * g1.y);
                    __half2 r2 = __floats2half2_rn(s[4] * g2.x, s[5] * g2.y);
                    __half2 r3 = __floats2half2_rn(s[6] * g3.x, s[7] * g3.y);
                    uint4 r;
                    r.x = *(uint32_t*)&r0; r.y = *(uint32_t*)&r1;
                    r.z = *(uint32_t*)&r2; r.w = *(uint32_t*)&r3;
                    xin4[b * (KCAT / 8) + (Ec / 8) + d8] = r;
                }
            } else if (idx < AWEH + EC8) {
                int i = idx - AWEH;
                int b = i / (Ec / 8), j = i % (Ec / 8);
                xin4[b * (KCAT / 8) + j] =
                    ((const uint4*)g_eseq16)[((size_t)b * Tc + t) * (Ec / 8) + j];
            } else {
                int i = idx - AWEH - EC8;
                int b = i / (Hc / 8), j = i % (Hc / 8);
                xin4[b * (KCAT / 8) + ((Ec + Dc) / 8) + j] =
                    ((const uint4*)g_h16)[b * (Hc / 8) + j];
            }
        }
        grid_bar(nb);

        // ---- Phase D: gates partials = xin @ wcatT (split-K=4) ----
        for (int u = blockIdx.x; u < 2 * 32 * NSPL; u += (int)nb) {
            int z = u & (NSPL - 1), uu = u >> 2;
            int row0 = (uu / 32) * 64, col0 = (uu % 32) * 64;
            float acc[2][2][4];
            gemm_core(sm, g_xin16 + (size_t)row0 * KCAT + z * (KCAT / NSPL),
                      g_wcatT + (size_t)col0 * KCAT + z * (KCAT / NSPL),
                      (KCAT / NSPL) >> 5, KCAT, KCAT, acc);
            int mbase = row0 + wm * 32, nbase = col0 + wn * 16;
            float* gz = g_gates[z];
            #pragma unroll
            for (int mf = 0; mf < 2; mf++)
                #pragma unroll
                for (int hr = 0; hr < 2; hr++) {
                    int m = mbase + mf * 16 + (lane >> 2) + hr * 8;
                    #pragma unroll
                    for (int nf = 0; nf < 2; nf++)
                        #pragma unroll
                        for (int e = 0; e < 2; e++) {
                            int n = nbase + nf * 8 + (lane & 3) * 2 + e;
                            gz[(size_t)m * (4 * Hc) + n] = acc[mf][nf][hr * 2 + e];
                        }
                }
        }
        grid_bar(nb);

        // ---- Phase E: LSTM pointwise ----
        for (int idx = gid; idx < Bc * Hc; idx += gsize) {
            int b = idx / Hc, j = idx % Hc;
            size_t base = (size_t)b * 4 * Hc;
            float i_ = g_bcat[j],          f_ = g_bcat[Hc + j];
            float gg = g_bcat[2 * Hc + j], o_ = g_bcat[3 * Hc + j];
            #pragma unroll
            for (int z = 0; z < NSPL; z++) {
                const float* gr = g_gates[z] + base;
                i_ += gr[j];
                f_ += gr[Hc + j];
                gg += gr[2 * Hc + j];
                o_ += gr[3 * Hc + j];
            }
            float cn = sigf(f_) * g_c[idx] + sigf(i_) * tanhf(gg);
            float hn = sigf(o_) * tanhf(cn);
            g_hn16[t][idx] = __float2half_rn(hn);
            if (t < lengths[b] - 1) {
                g_h16[idx] = __float2half_rn(hn);
                g_c[idx] = cn;
            }
        }
        grid_bar(nb);
    }
}

// ---------------- template GEMM for prologue + batched cls -------------------
// mode 0: plain bias (+C/C16). mode 3: batched cls (row m -> t=m>>7, b=m&127).
template<int BM, int BN>
__global__ void __launch_bounds__(256) gemm_mma(
    const __half* __restrict__ A, const __half* __restrict__ Bt,
    const float* __restrict__ bias, float* __restrict__ C, __half* __restrict__ C16,
    int M, int N, int K, int ldc, int ld16, int mode,
    const int* __restrict__ lengths)
{
    constexpr int MFRAG = BM / 32;
    constexpr int NFRAG = BN / 32;
    __shared__ __half sA[2][BM * ASTR];
    __shared__ __half sB[2][BN * ASTR];

    const int tid = threadIdx.x;
    const int lane = tid & 31, warp = tid >> 5;
    const int wm = warp >> 2, wn = warp & 3;
    const int row0 = blockIdx.y * BM, col0 = blockIdx.x * BN;

    const __half* Ab = A + (size_t)row0 * K;
    const __half* Bb = Bt + (size_t)col0 * K;
    const int nk = K >> 5;

    const uint32_t sAu = smem_u32(sA);
    const uint32_t sBu = smem_u32(sB);

    float acc[MFRAG][NFRAG][4];
    #pragma unroll
    for (int i = 0; i < MFRAG; i++)
        #pragma unroll
        for (int j = 0; j < NFRAG; j++)
            #pragma unroll
            for (int e = 0; e < 4; e++) acc[i][j][e] = 0.f;

    const int aRow = wm * (BM / 2) + (lane & 15);
    const int aCol = (lane >= 16) ? 8 : 0;
    const int bRow = wn * (BN / 4) + (lane & 7);
    const int bCol = ((lane & 15) >= 8) ? 8 : 0;

    {
        #pragma unroll
        for (int l = 0; l < BM / 64; l++) {
            int c = tid + l * 256;
            int r = c >> 2, q = c & 3;
            cp16(sAu + (uint32_t)(r * ASTR + q * 8) * 2, Ab + (size_t)r * K + q * 8);
        }
        #pragma unroll
        for (int l = 0; l < BN / 64; l++) {
            int c = tid + l * 256;
            int r = c >> 2, q = c & 3;
            cp16(sBu + (uint32_t)(r * ASTR + q * 8) * 2, Bb + (size_t)r * K + q * 8);
        }
    }
    CP_COMMIT();

    for (int i = 0; i < nk; i++) {
        int buf = i & 1;
        if (i + 1 < nk) {
            int nbuf = buf ^ 1;
            int k0 = (i + 1) << 5;
            #pragma unroll
            for (int l = 0; l < BM / 64; l++) {
                int c = tid + l * 256;
                int r = c >> 2, q = c & 3;
                cp16(sAu + (uint32_t)(nbuf * BM * ASTR + r * ASTR + q * 8) * 2,
                     Ab + (size_t)r * K + k0 + q * 8);
            }
            #pragma unroll
            for (int l = 0; l < BN / 64; l++) {
                int c = tid + l * 256;
                int r = c >> 2, q = c & 3;
                cp16(sBu + (uint32_t)(nbuf * BN * ASTR + r * ASTR + q * 8) * 2,
                     Bb + (size_t)r * K + k0 + q * 8);
            }
            CP_COMMIT();
            asm volatile("cp.async.wait_group 1;" ::: "memory");
        } else {
            asm volatile("cp.async.wait_group 0;" ::: "memory");
        }
        __syncthreads();

        uint32_t baseA = sAu + (uint32_t)(buf * BM * ASTR) * 2;
        uint32_t baseB = sBu + (uint32_t)(buf * BN * ASTR) * 2;
        #pragma unroll
        for (int ks = 0; ks < 32; ks += 16) {
            uint32_t a[MFRAG][4], b[NFRAG][2];
            #pragma unroll
            for (int mf = 0; mf < MFRAG; mf++) {
                uint32_t addr = baseA + (uint32_t)((aRow + mf * 16) * ASTR + ks + aCol) * 2;
                asm volatile("ldmatrix.sync.aligned.m8n8.x4.shared.b16 {%0,%1,%2,%3}, [%4];"
                             : "=r"(a[mf][0]), "=r"(a[mf][1]), "=r"(a[mf][2]), "=r"(a[mf][3])
                             : "r"(addr));
            }
            #pragma unroll
            for (int nf = 0; nf < NFRAG; nf++) {
                uint32_t addr = baseB + (uint32_t)((bRow + nf * 8) * ASTR + ks + bCol) * 2;
                asm volatile("ldmatrix.sync.aligned.m8n8.x2.shared.b16 {%0,%1}, [%2];"
                             : "=r"(b[nf][0]), "=r"(b[nf][1]) : "r"(addr));
            }
            #pragma unroll
            for (int mf = 0; mf < MFRAG; mf++)
                #pragma unroll
                for (int nf = 0; nf < NFRAG; nf++) {
                    float* cc = acc[mf][nf];
                    asm volatile(
                        "mma.sync.aligned.m16n8k16.row.col.f32.f16.f16.f32 "
                        "{%0,%1,%2,%3}, {%4,%5,%6,%7}, {%8,%9}, {%0,%1,%2,%3};"
                        : "+f"(cc[0]), "+f"(cc[1]), "+f"(cc[2]), "+f"(cc[3])
                        : "r"(a[mf][0]), "r"(a[mf][1]), "r"(a[mf][2]), "r"(a[mf][3]),
                          "r"(b[nf][0]), "r"(b[nf][1]));
                }
        }
        __syncthreads();
    }

    const int mbase = row0 + wm * (BM / 2);
    const int nbase = col0 + wn * (BN / 4);
    #pragma unroll
    for (int mf = 0; mf < MFRAG; mf++) {
        #pragma unroll
        for (int hr = 0; hr < 2; hr++) {
            int m = mbase + mf * 16 + (lane >> 2) + hr * 8;
            #pragma unroll
            for (int nf = 0; nf < NFRAG; nf++) {
                #pragma unroll
                for (int e = 0; e < 2; e++) {
                    int n = nbase + nf * 8 + (lane & 3) * 2 + e;
                    if (n < N) {
                        float v = acc[mf][nf][hr * 2 + e];
                        if (bias) v += bias[n];
                        if (mode == 3) {
                            int tt = m >> 7, bb = m & 127;
                            float mk = (tt < lengths[bb] - 1) ? 1.f : 0.f;
                            C[((size_t)bb * Tc + tt) * Vc + n] = v * mk;
                        } else {
                            if (C)   C[(size_t)m * ldc + n] = v;
                            if (C16) C16[(size_t)m * ld16 + n] = __float2half_rn(v);
                        }
                    }
                }
            }
        }
    }
}

// ---------------- support kernels -------------------------------------------

__global__ void f32to16_kernel(const float* __restrict__ in, __half* __restrict__ out, int n2) {
    int i = blockIdx.x * blockDim.x + threadIdx.x;
    if (i < n2) {
        float2 v = ((const float2*)in)[i];
        ((__half2*)out)[i] = __floats2half2_rn(v.x, v.y);
    }
}

__global__ void transpose16_kernel(const float* __restrict__ in, __half* __restrict__ out,
                                   int K, int N, int out_ld, int k_off) {
    __shared__ float tile[32][33];
    int kb = blockIdx.y * 32, nb = blockIdx.x * 32;
    int x = threadIdx.x, y = threadIdx.y;
    #pragma unroll
    for (int j = 0; j < 32; j += 8) {
        int k = kb + y + j, n = nb + x;
        tile[y + j][x] = (k < K && n < N) ? in[(size_t)k * N + n] : 0.f;
    }
    __syncthreads();
    #pragma unroll
    for (int j = 0; j < 32; j += 8) {
        int n = nb + y + j, k = kb + x;
        if (n < N && k < K) out[(size_t)n * out_ld + k_off + k] = __float2half_rn(tile[x][y + j]);
    }
}

__global__ void clspad_kernel() {
    int i = blockIdx.x * blockDim.x + threadIdx.x;
    int total = (VPAD2 - Vc) * Hc;
    if (i < total) g_clsT[(size_t)Vc * Hc + i] = __float2half_rn(0.f);
}

__global__ void bias_prep_kernel(const float* __restrict__ bi, const float* __restrict__ bh,
                                 const float* __restrict__ db, const float* __restrict__ bb) {
    int i = blockIdx.x * blockDim.x + threadIdx.x;
    if (i < 4 * Hc) g_bcat[i] = bi[i] + bh[i];
    if (i < NDB) g_dbbias[i] = (i < Ac) ? db[i] : bb[i - Ac];
}

__global__ void mean_kernel(const float* __restrict__ f) {
    int idx = blockIdx.x * blockDim.x + threadIdx.x;
    if (idx >= Bc * Dc) return;
    int b = idx / Dc, d = idx % Dc;
    const float* p = f + (size_t)b * Pc * Dc + d;
    float s = 0.f;
    #pragma unroll 4
    for (int i = 0; i < Pc; i++) s += p[(size_t)i * Dc];
    g_meanf16[idx] = __float2half_rn(s * (1.0f / Pc));
}

__global__ void embed_kernel(const float* __restrict__ emb, const int* __restrict__ cap) {
    int idx = blockIdx.x * blockDim.x + threadIdx.x;
    if (idx >= Bc * Tc * Ec) return;
    int j = idx % Ec;
    int bt = idx / Ec;
    int t = bt % Tc;
    int b = bt / Tc;
    int tok = cap[b * TMAXc + t];
    g_eseq16[idx] = __float2half_rn(emb[(size_t)tok * Ec + j]);
}

// ---------------- launcher ---------------------------------------------------

static void transL(const float* in, __half* out, int K, int N, int out_ld, int k_off) {
    dim3 grid((N + 31) / 32, (K + 31) / 32);
    transpose16_kernel<<<grid, dim3(32, 8)>>>(in, out, K, N, out_ld, k_off);
}

extern "C" void kernel_launch(void* const* d_in, const int* in_sizes, int n_in,
                              void* d_out, int out_size) {
    const float* features = (const float*)d_in[0];
    const int*   captions = (const int*)d_in[1];
    const int*   lengths  = (const int*)d_in[2];
    const float* emb      = (const float*)d_in[3];
    const float* h_fc_w   = (const float*)d_in[4];
    const float* h_fc_b   = (const float*)d_in[5];
    const float* c_fc_w   = (const float*)d_in[6];
    const float* c_fc_b   = (const float*)d_in[7];
    const float* enc_w    = (const float*)d_in[8];
    const float* enc_b    = (const float*)d_in[9];
    const float* dec_w    = (const float*)d_in[10];
    const float* dec_b    = (const float*)d_in[11];
    const float* att_w    = (const float*)d_in[12];
    const float* att_b    = (const float*)d_in[13];
    const float* beta_w   = (const float*)d_in[14];
    const float* beta_b   = (const float*)d_in[15];
    const float* w_ih     = (const float*)d_in[16];
    const float* b_ih     = (const float*)d_in[17];
    const float* w_hh     = (const float*)d_in[18];
    const float* b_hh     = (const float*)d_in[19];
    const float* cls_w    = (const float*)d_in[20];
    const float* cls_b    = (const float*)d_in[21];

    float* out = (float*)d_out;
    float* y_out = out;                               // (B, T, V)
    float* a_out = out + (size_t)Bc * Tc * Vc;        // (B, T, P)

    __half *feat16, *meanf16, *h16, *hn16, *att1_16;
    __half *hfcT, *cfcT, *encT, *dbT, *wcatT, *clsT;
    float *cst;
    cudaGetSymbolAddress((void**)&feat16,  g_feat16);
    cudaGetSymbolAddress((void**)&meanf16, g_meanf16);
    cudaGetSymbolAddress((void**)&h16,     g_h16);
    cudaGetSymbolAddress((void**)&hn16,    g_hn16);
    cudaGetSymbolAddress((void**)&att1_16, g_att1_16);
    cudaGetSymbolAddress((void**)&hfcT,    g_hfcT);
    cudaGetSymbolAddress((void**)&cfcT,    g_cfcT);
    cudaGetSymbolAddress((void**)&encT,    g_encT);
    cudaGetSymbolAddress((void**)&dbT,     g_dbT);
    cudaGetSymbolAddress((void**)&wcatT,   g_wcatT);
    cudaGetSymbolAddress((void**)&clsT,    g_clsT);
    cudaGetSymbolAddress((void**)&cst,     g_c);

    // persistent-kernel grid: full residency (R11 config — best measured)
    int smcount = 0, occ = 0;
    cudaDeviceGetAttribute(&smcount, cudaDevAttrMultiProcessorCount, 0);
    cudaOccupancyMaxActiveBlocksPerMultiprocessor(&occ, step_loop_kernel, 256, 0);
    if (occ < 1) occ = 1;
    if (occ > 2) occ = 2;
    int nb = smcount * occ;

    // ---- prologue --------------------------------------------------------
    f32to16_kernel<<<((Bc * Pc * Dc / 2) + 255) / 256, 256>>>(features, feat16, Bc * Pc * Dc / 2);
    transL(h_fc_w, hfcT, Dc, Hc, Dc, 0);
    transL(c_fc_w, cfcT, Dc, Hc, Dc, 0);
    transL(enc_w,  encT, Dc, Ac, Dc, 0);
    transL(dec_w,  dbT, Hc, Ac, Hc, 0);
    transL(beta_w, dbT + (size_t)Ac * Hc, Hc, Dc, Hc, 0);
    transL(w_ih,   wcatT, Dc + Ec, 4 * Hc, KCAT, 0);
    transL(w_hh,   wcatT, Hc, 4 * Hc, KCAT, Dc + Ec);
    transL(cls_w,  clsT, Hc, Vc, Hc, 0);
    clspad_kernel<<<(((VPAD2 - Vc) * Hc) + 255) / 256, 256>>>();
    bias_prep_kernel<<<(NDB + 255) / 256, 256>>>(b_ih, b_hh, dec_b, beta_b);
    mean_kernel<<<(Bc * Dc + 255) / 256, 256>>>(features);
    embed_kernel<<<(Bc * Tc * Ec + 255) / 256, 256>>>(emb, captions);

    // h0 / c0 / att1
    {
        dim3 g1(Hc / 64, Bc / 64);
        gemm_mma<64, 64><<<g1, 256>>>(meanf16, hfcT, h_fc_b, nullptr, h16, Bc, Hc, Dc, 0, Hc, 0, nullptr);
        gemm_mma<64, 64><<<g1, 256>>>(meanf16, cfcT, c_fc_b, cst, nullptr, Bc, Hc, Dc, Hc, 0, 0, nullptr);
        dim3 g2(Ac / 128, (Bc * Pc) / 64);
        gemm_mma<64, 128><<<g2, 256>>>(feat16, encT, enc_b, nullptr, att1_16, Bc * Pc, Ac, Dc, 0, Ac, 0, nullptr);
    }

    // ---- persistent 19-step loop -----------------------------------------
    step_loop_kernel<<<nb, 256>>>(att_w, att_b, lengths, a_out);

    // ---- batched cls over all steps: (Tc*Bc, Vc) = hn_all @ clsT ---------
    {
        dim3 g3((Vc + 127) / 128, (Tc * Bc) / 64);
        gemm_mma<64, 128><<<g3, 256>>>(hn16, clsT, cls_b, y_out, nullptr,
                                       Tc * Bc, Vc, Hc, 0, 0, 3, lengths);
    }
}

// round 17
// speedup vs baseline: 1.2037x; 1.0249x over previous
#include <cuda_runtime.h>
#include <cuda_fp16.h>
#include <math.h>
#include <stdint.h>

// Problem constants
#define Bc 128
#define Pc 196
#define Dc 2048
#define Ac 512
#define Ec 512
#define Hc 512
#define Vc 10000
#define Tc 19
#define TMAXc 20
#define KCAT 3072   // E + D + H for fused gates GEMM
#define NDB 2560    // A + D for merged dec+beta GEMM
#define VPAD2 10112 // Vc padded to multiple of 128 (B-tile overread safety)
#define NSPL 4      // split-K for gates GEMM inside persistent kernel

// ---------------- scratch (device globals; no allocation allowed) ----------
__device__ __half g_feat16[(size_t)Bc * Pc * Dc];
__device__ __half g_meanf16[Bc * Dc];
__device__ __half g_h16[Bc * Hc];
__device__ float  g_c[Bc * Hc];
__device__ __half g_hn16[Tc][Bc * Hc];                // per-step hn for batched cls
__device__ __half g_att1_16[(size_t)Bc * Pc * Ac];
__device__ __half g_eseq16[(size_t)Bc * Tc * Ec];
__device__ float  g_att2[Bc * Ac];
__device__ float  g_alpha[Bc * Pc];
__device__ __half g_gate16[Bc * Dc];
__device__ __half g_xin16[Bc * KCAT];
__device__ float  g_gates[NSPL][Bc * 4 * Hc];
// transposed fp16 weights (K-major B operands: Bt[n][k])
__device__ __half g_hfcT[Hc * Dc];
__device__ __half g_cfcT[Hc * Dc];
__device__ __half g_encT[Ac * Dc];
__device__ __half g_dbT[(size_t)NDB * Hc];
__device__ float  g_dbbias[NDB];
__device__ __half g_wcatT[(size_t)(4 * Hc) * KCAT];
__device__ __half g_clsT[(size_t)VPAD2 * Hc];
__device__ float  g_bcat[4 * Hc];
// software grid barrier state
__device__ unsigned g_bar_count = 0;
__device__ unsigned g_bar_gen = 0;

// ---------------- helpers ---------------------------------------------------
__device__ __forceinline__ uint32_t smem_u32(const void* p) {
    uint32_t a;
    asm("{ .reg .u64 t; cvta.to.shared.u64 t, %1; cvt.u32.u64 %0, t; }" : "=r"(a) : "l"(p));
    return a;
}
__device__ __forceinline__ void cp16(uint32_t dst, const void* src) {
    asm volatile("cp.async.ca.shared.global [%0], [%1], 16;" :: "r"(dst), "l"(src));
}
#define CP_COMMIT() asm volatile("cp.async.commit_group;" ::: "memory")

__device__ __forceinline__ float sigf(float x) { return 1.f / (1.f + expf(-x)); }

__device__ __forceinline__ void grid_bar(unsigned nb) {
    __syncthreads();
    if (threadIdx.x == 0) {
        __threadfence();
        unsigned gen = atomicAdd(&g_bar_gen, 0u);
        unsigned prev = atomicAdd(&g_bar_count, 1u);
        if (prev == nb - 1) {
            atomicExch(&g_bar_count, 0u);
            __threadfence();
            atomicAdd(&g_bar_gen, 1u);
        } else {
            while (atomicAdd(&g_bar_gen, 0u) == gen) __nanosleep(64);
        }
        __threadfence();
    }
    __syncthreads();
}

#define ASTR 40
struct GemmSm { __half A[2][64 * ASTR]; __half B[2][64 * ASTR]; };   // 20480 B
struct AttSm  { float s2[Ac]; float sw[Ac]; float se[224]; float red[256]; };
union SmemU { GemmSm g; AttSm a; };

// 64x64 double-buffered mma core; all 256 threads participate.
__device__ __forceinline__ void gemm_core(SmemU& sm,
    const __half* __restrict__ Ab, const __half* __restrict__ Bb,
    int nk, int lda, int ldb, float acc[2][2][4])
{
    const int tid = threadIdx.x;
    const int lane = tid & 31, warp = tid >> 5;
    const int wm = warp >> 2, wn = warp & 3;
    const uint32_t sAu = smem_u32(sm.g.A);
    const uint32_t sBu = smem_u32(sm.g.B);
    const int aRow = wm * 32 + (lane & 15);
    const int aCol = (lane >= 16) ? 8 : 0;
    const int bRow = wn * 16 + (lane & 7);
    const int bCol = ((lane & 15) >= 8) ? 8 : 0;
    const int lr = tid >> 2, lq = tid & 3;

    #pragma unroll
    for (int i = 0; i < 2; i++)
        #pragma unroll
        for (int j = 0; j < 2; j++)
            #pragma unroll
            for (int e = 0; e < 4; e++) acc[i][j][e] = 0.f;

    cp16(sAu + (uint32_t)(lr * ASTR + lq * 8) * 2, Ab + (size_t)lr * lda + lq * 8);
    cp16(sBu + (uint32_t)(lr * ASTR + lq * 8) * 2, Bb + (size_t)lr * ldb + lq * 8);
    CP_COMMIT();

    for (int i = 0; i < nk; i++) {
        int buf = i & 1;
        if (i + 1 < nk) {
            int nbuf = buf ^ 1;
            int k0 = (i + 1) << 5;
            cp16(sAu + (uint32_t)(nbuf * 64 * ASTR + lr * ASTR + lq * 8) * 2,
                 Ab + (size_t)lr * lda + k0 + lq * 8);
            cp16(sBu + (uint32_t)(nbuf * 64 * ASTR + lr * ASTR + lq * 8) * 2,
                 Bb + (size_t)lr * ldb + k0 + lq * 8);
            CP_COMMIT();
            asm volatile("cp.async.wait_group 1;" ::: "memory");
        } else {
            asm volatile("cp.async.wait_group 0;" ::: "memory");
        }
        __syncthreads();
        uint32_t baseA = sAu + (uint32_t)(buf * 64 * ASTR) * 2;
        uint32_t baseB = sBu + (uint32_t)(buf * 64 * ASTR) * 2;
        #pragma unroll
        for (int ks = 0; ks < 32; ks += 16) {
            uint32_t a[2][4], b[2][2];
            #pragma unroll
            for (int mf = 0; mf < 2; mf++) {
                uint32_t addr = baseA + (uint32_t)((aRow + mf * 16) * ASTR + ks + aCol) * 2;
                asm volatile("ldmatrix.sync.aligned.m8n8.x4.shared.b16 {%0,%1,%2,%3}, [%4];"
                             : "=r"(a[mf][0]), "=r"(a[mf][1]), "=r"(a[mf][2]), "=r"(a[mf][3])
                             : "r"(addr));
            }
            #pragma unroll
            for (int nf = 0; nf < 2; nf++) {
                uint32_t addr = baseB + (uint32_t)((bRow + nf * 8) * ASTR + ks + bCol) * 2;
                asm volatile("ldmatrix.sync.aligned.m8n8.x2.shared.b16 {%0,%1}, [%2];"
                             : "=r"(b[nf][0]), "=r"(b[nf][1]) : "r"(addr));
            }
            #pragma unroll
            for (int mf = 0; mf < 2; mf++)
                #pragma unroll
                for (int nf = 0; nf < 2; nf++) {
                    float* cc = acc[mf][nf];
                    asm volatile(
                        "mma.sync.aligned.m16n8k16.row.col.f32.f16.f16.f32 "
                        "{%0,%1,%2,%3}, {%4,%5,%6,%7}, {%8,%9}, {%0,%1,%2,%3};"
                        : "+f"(cc[0]), "+f"(cc[1]), "+f"(cc[2]), "+f"(cc[3])
                        : "r"(a[mf][0]), "r"(a[mf][1]), "r"(a[mf][2]), "r"(a[mf][3]),
                          "r"(b[nf][0]), "r"(b[nf][1]));
                }
        }
        __syncthreads();
    }
}

// ---------------- persistent step-loop kernel --------------------------------
#define AWEQ (Bc * Dc / 2)   // 131072 quarter-column work items (4 per (b,d8))
#define EC8  (Bc * Ec / 8)
#define HC8  (Bc * Hc / 8)
__device__ __forceinline__ void h2acc(uint32_t h2, float a, float& x, float& y) {
    float2 v = __half22float2(*(__half2*)&h2);
    x += a * v.x;
    y += a * v.y;
}

__global__ void __launch_bounds__(256, 2) step_loop_kernel(
    const float* __restrict__ att_w, const float* __restrict__ att_b,
    const int* __restrict__ lengths, float* __restrict__ a_out)
{
    __shared__ SmemU sm;
    const int tid = threadIdx.x;
    const int lane = tid & 31, warp = tid >> 5;
    const int wm = warp >> 2, wn = warp & 3;
    const unsigned nb = gridDim.x;
    const int gsize = (int)nb * 256;
    const int gid = blockIdx.x * 256 + tid;

    for (int t = 0; t < Tc; t++) {
        // ---- Phase A: [att2 | gate] = h @ dbT (blocks 0..79) +
        //      xin e_t/h copies (idle blocks >= 80; deps: eseq[t], prev h) ----
        if (blockIdx.x < 80) {
            int u = blockIdx.x;
            int row0 = (u / 40) * 64, col0 = (u % 40) * 64;
            float acc[2][2][4];
            gemm_core(sm, g_h16 + (size_t)row0 * Hc, g_dbT + (size_t)col0 * Hc,
                      Hc >> 5, Hc, Hc, acc);
            int mbase = row0 + wm * 32, nbase = col0 + wn * 16;
            #pragma unroll
            for (int mf = 0; mf < 2; mf++)
                #pragma unroll
                for (int hr = 0; hr < 2; hr++) {
                    int m = mbase + mf * 16 + (lane >> 2) + hr * 8;
                    #pragma unroll
                    for (int nf = 0; nf < 2; nf++)
                        #pragma unroll
                        for (int e = 0; e < 2; e++) {
                            int n = nbase + nf * 8 + (lane & 3) * 2 + e;
                            float v = acc[mf][nf][hr * 2 + e] + g_dbbias[n];
                            if (n < Ac) g_att2[m * Ac + n] = v;
                            else g_gate16[m * Dc + (n - Ac)] = __float2half_rn(sigf(v));
                        }
                }
        } else {
            uint4* xin4 = (uint4*)g_xin16;
            int cid = (blockIdx.x - 80) * 256 + tid;
            int csz = ((int)nb - 80) * 256;
            for (int idx = cid; idx < EC8 + HC8; idx += csz) {
                if (idx < EC8) {
                    int b = idx / (Ec / 8), j = idx % (Ec / 8);
                    xin4[b * (KCAT / 8) + j] =
                        ((const uint4*)g_eseq16)[((size_t)b * Tc + t) * (Ec / 8) + j];
                } else {
                    int i = idx - EC8;
                    int b = i / (Hc / 8), j = i % (Hc / 8);
                    xin4[b * (KCAT / 8) + ((Ec + Dc) / 8) + j] =
                        ((const uint4*)g_h16)[b * (Hc / 8) + j];
                }
            }
        }
        grid_bar(nb);

        // ---- Phase B: e = relu(att1 + att2) @ att_w + att_b; softmax ----
        for (int b = blockIdx.x; b < Bc; b += (int)nb) {
            for (int i = tid; i < Ac; i += 256) {
                sm.a.s2[i] = g_att2[b * Ac + i];
                sm.a.sw[i] = att_w[i];
            }
            __syncthreads();
            float attb = att_b[0];
            for (int p = warp; p < Pc; p += 8) {
                const __half2* a1 = (const __half2*)(g_att1_16 + ((size_t)b * Pc + p) * Ac);
                float s = 0.f;
                #pragma unroll
                for (int k = 0; k < 8; k++) {
                    int h2i = lane + 32 * k;
                    float2 v = __half22float2(a1[h2i]);
                    int a0 = 2 * h2i;
                    s += fmaxf(v.x + sm.a.s2[a0], 0.f) * sm.a.sw[a0];
                    s += fmaxf(v.y + sm.a.s2[a0 + 1], 0.f) * sm.a.sw[a0 + 1];
                }
                #pragma unroll
                for (int o = 16; o > 0; o >>= 1) s += __shfl_xor_sync(0xffffffffu, s, o);
                if (lane == 0) sm.a.se[p] = s + attb;
            }
            __syncthreads();
            float v = (tid < Pc) ? sm.a.se[tid] : -1e30f;
            sm.a.red[tid] = v;
            __syncthreads();
            for (int s = 128; s > 0; s >>= 1) {
                if (tid < s) sm.a.red[tid] = fmaxf(sm.a.red[tid], sm.a.red[tid + s]);
                __syncthreads();
            }
            float mx = sm.a.red[0];
            __syncthreads();
            float ex = (tid < Pc) ? expf(v - mx) : 0.f;
            sm.a.red[tid] = ex;
            __syncthreads();
            for (int s = 128; s > 0; s >>= 1) {
                if (tid < s) sm.a.red[tid] += sm.a.red[tid + s];
                __syncthreads();
            }
            float inv = 1.0f / sm.a.red[0];
            if (tid < Pc) {
                float al = ex * inv;
                g_alpha[b * Pc + tid] = al;
                float mf = (t < lengths[b] - 1) ? 1.f : 0.f;
                a_out[((size_t)b * Tc + t) * Pc + tid] = al * mf;
            }
            __syncthreads();
        }
        grid_bar(nb);

        // ---- Phase C: xin[D] = gate * (alpha @ features) ----
        // 4-way lane-quad split: quarter q sums p in [49q, 49q+49);
        // combined via two shfl_down steps. Quads never straddle warps.
        for (int idx = gid; idx < AWEQ; idx += gsize) {
            int quart = idx & 3;
            int pair = idx >> 2;
            int b = pair / (Dc / 8), d8 = pair % (Dc / 8);
            const uint4* fp = ((const uint4*)g_feat16)
                + (size_t)b * Pc * (Dc / 8) + (size_t)(quart * 49) * (Dc / 8) + d8;
            const float* al = g_alpha + b * Pc + quart * 49;
            float s[8] = {0.f, 0.f, 0.f, 0.f, 0.f, 0.f, 0.f, 0.f};
            #pragma unroll 7
            for (int p = 0; p < 49; p++) {
                float a = al[p];
                uint4 v = fp[(size_t)p * (Dc / 8)];
                h2acc(v.x, a, s[0], s[1]);
                h2acc(v.y, a, s[2], s[3]);
                h2acc(v.z, a, s[4], s[5]);
                h2acc(v.w, a, s[6], s[7]);
            }
            #pragma unroll
            for (int k = 0; k < 8; k++) {
                s[k] += __shfl_down_sync(0xffffffffu, s[k], 2);
                s[k] += __shfl_down_sync(0xffffffffu, s[k], 1);
            }
            if (quart == 0) {
                uint4 g4 = ((const uint4*)g_gate16)[b * (Dc / 8) + d8];
                float2 g0 = __half22float2(*(__half2*)&g4.x);
                float2 g1 = __half22float2(*(__half2*)&g4.y);
                float2 g2 = __half22float2(*(__half2*)&g4.z);
                float2 g3 = __half22float2(*(__half2*)&g4.w);
                __half2 r0 = __floats2half2_rn(s[0] * g0.x, s[1] * g0.y);
                __half2 r1 = __floats2half2_rn(s[2] * g1.x, s[3] * g1.y);
                __half2 r2 = __floats2half2_rn(s[4] * g2.x, s[5] * g2.y);
                __half2 r3 = __floats2half2_rn(s[6] * g3.x, s[7] * g3.y);
                uint4 r;
                r.x = *(uint32_t*)&r0; r.y = *(uint32_t*)&r1;
                r.z = *(uint32_t*)&r2; r.w = *(uint32_t*)&r3;
                ((uint4*)g_xin16)[b * (KCAT / 8) + (Ec / 8) + d8] = r;
            }
        }
        grid_bar(nb);

        // ---- Phase D: gates partials = xin @ wcatT (split-K=4) ----
        for (int u = blockIdx.x; u < 2 * 32 * NSPL; u += (int)nb) {
            int z = u & (NSPL - 1), uu = u >> 2;
            int row0 = (uu / 32) * 64, col0 = (uu % 32) * 64;
            float acc[2][2][4];
            gemm_core(sm, g_xin16 + (size_t)row0 * KCAT + z * (KCAT / NSPL),
                      g_wcatT + (size_t)col0 * KCAT + z * (KCAT / NSPL),
                      (KCAT / NSPL) >> 5, KCAT, KCAT, acc);
            int mbase = row0 + wm * 32, nbase = col0 + wn * 16;
            float* gz = g_gates[z];
            #pragma unroll
            for (int mf = 0; mf < 2; mf++)
                #pragma unroll
                for (int hr = 0; hr < 2; hr++) {
                    int m = mbase + mf * 16 + (lane >> 2) + hr * 8;
                    #pragma unroll
                    for (int nf = 0; nf < 2; nf++)
                        #pragma unroll
                        for (int e = 0; e < 2; e++) {
                            int n = nbase + nf * 8 + (lane & 3) * 2 + e;
                            gz[(size_t)m * (4 * Hc) + n] = acc[mf][nf][hr * 2 + e];
                        }
                }
        }
        grid_bar(nb);

        // ---- Phase E: LSTM pointwise ----
        for (int idx = gid; idx < Bc * Hc; idx += gsize) {
            int b = idx / Hc, j = idx % Hc;
            size_t base = (size_t)b * 4 * Hc;
            float i_ = g_bcat[j],          f_ = g_bcat[Hc + j];
            float gg = g_bcat[2 * Hc + j], o_ = g_bcat[3 * Hc + j];
            #pragma unroll
            for (int z = 0; z < NSPL; z++) {
                const float* gr = g_gates[z] + base;
                i_ += gr[j];
                f_ += gr[Hc + j];
                gg += gr[2 * Hc + j];
                o_ += gr[3 * Hc + j];
            }
            float cn = sigf(f_) * g_c[idx] + sigf(i_) * tanhf(gg);
            float hn = sigf(o_) * tanhf(cn);
            g_hn16[t][idx] = __float2half_rn(hn);
            if (t < lengths[b] - 1) {
                g_h16[idx] = __float2half_rn(hn);
                g_c[idx] = cn;
            }
        }
        grid_bar(nb);
    }
}

// ---------------- template GEMM for prologue + batched cls -------------------
// mode 0: plain bias (+C/C16). mode 3: batched cls (row m -> t=m>>7, b=m&127).
template<int BM, int BN>
__global__ void __launch_bounds__(256) gemm_mma(
    const __half* __restrict__ A, const __half* __restrict__ Bt,
    const float* __restrict__ bias, float* __restrict__ C, __half* __restrict__ C16,
    int M, int N, int K, int ldc, int ld16, int mode,
    const int* __restrict__ lengths)
{
    constexpr int MFRAG = BM / 32;
    constexpr int NFRAG = BN / 32;
    __shared__ __half sA[2][BM * ASTR];
    __shared__ __half sB[2][BN * ASTR];

    const int tid = threadIdx.x;
    const int lane = tid & 31, warp = tid >> 5;
    const int wm = warp >> 2, wn = warp & 3;
    const int row0 = blockIdx.y * BM, col0 = blockIdx.x * BN;

    const __half* Ab = A + (size_t)row0 * K;
    const __half* Bb = Bt + (size_t)col0 * K;
    const int nk = K >> 5;

    const uint32_t sAu = smem_u32(sA);
    const uint32_t sBu = smem_u32(sB);

    float acc[MFRAG][NFRAG][4];
    #pragma unroll
    for (int i = 0; i < MFRAG; i++)
        #pragma unroll
        for (int j = 0; j < NFRAG; j++)
            #pragma unroll
            for (int e = 0; e < 4; e++) acc[i][j][e] = 0.f;

    const int aRow = wm * (BM / 2) + (lane & 15);
    const int aCol = (lane >= 16) ? 8 : 0;
    const int bRow = wn * (BN / 4) + (lane & 7);
    const int bCol = ((lane & 15) >= 8) ? 8 : 0;

    {
        #pragma unroll
        for (int l = 0; l < BM / 64; l++) {
            int c = tid + l * 256;
            int r = c >> 2, q = c & 3;
            cp16(sAu + (uint32_t)(r * ASTR + q * 8) * 2, Ab + (size_t)r * K + q * 8);
        }
        #pragma unroll
        for (int l = 0; l < BN / 64; l++) {
            int c = tid + l * 256;
            int r = c >> 2, q = c & 3;
            cp16(sBu + (uint32_t)(r * ASTR + q * 8) * 2, Bb + (size_t)r * K + q * 8);
        }
    }
    CP_COMMIT();

    for (int i = 0; i < nk; i++) {
        int buf = i & 1;
        if (i + 1 < nk) {
            int nbuf = buf ^ 1;
            int k0 = (i + 1) << 5;
            #pragma unroll
            for (int l = 0; l < BM / 64; l++) {
                int c = tid + l * 256;
                int r = c >> 2, q = c & 3;
                cp16(sAu + (uint32_t)(nbuf * BM * ASTR + r * ASTR + q * 8) * 2,
                     Ab + (size_t)r * K + k0 + q * 8);
            }
            #pragma unroll
            for (int l = 0; l < BN / 64; l++) {
                int c = tid + l * 256;
                int r = c >> 2, q = c & 3;
                cp16(sBu + (uint32_t)(nbuf * BN * ASTR + r * ASTR + q * 8) * 2,
                     Bb + (size_t)r * K + k0 + q * 8);
            }
            CP_COMMIT();
            asm volatile("cp.async.wait_group 1;" ::: "memory");
        } else {
            asm volatile("cp.async.wait_group 0;" ::: "memory");
        }
        __syncthreads();

        uint32_t baseA = sAu + (uint32_t)(buf * BM * ASTR) * 2;
        uint32_t baseB = sBu + (uint32_t)(buf * BN * ASTR) * 2;
        #pragma unroll
        for (int ks = 0; ks < 32; ks += 16) {
            uint32_t a[MFRAG][4], b[NFRAG][2];
            #pragma unroll
            for (int mf = 0; mf < MFRAG; mf++) {
                uint32_t addr = baseA + (uint32_t)((aRow + mf * 16) * ASTR + ks + aCol) * 2;
                asm volatile("ldmatrix.sync.aligned.m8n8.x4.shared.b16 {%0,%1,%2,%3}, [%4];"
                             : "=r"(a[mf][0]), "=r"(a[mf][1]), "=r"(a[mf][2]), "=r"(a[mf][3])
                             : "r"(addr));
            }
            #pragma unroll
            for (int nf = 0; nf < NFRAG; nf++) {
                uint32_t addr = baseB + (uint32_t)((bRow + nf * 8) * ASTR + ks + bCol) * 2;
                asm volatile("ldmatrix.sync.aligned.m8n8.x2.shared.b16 {%0,%1}, [%2];"
                             : "=r"(b[nf][0]), "=r"(b[nf][1]) : "r"(addr));
            }
            #pragma unroll
            for (int mf = 0; mf < MFRAG; mf++)
                #pragma unroll
                for (int nf = 0; nf < NFRAG; nf++) {
                    float* cc = acc[mf][nf];
                    asm volatile(
                        "mma.sync.aligned.m16n8k16.row.col.f32.f16.f16.f32 "
                        "{%0,%1,%2,%3}, {%4,%5,%6,%7}, {%8,%9}, {%0,%1,%2,%3};"
                        : "+f"(cc[0]), "+f"(cc[1]), "+f"(cc[2]), "+f"(cc[3])
                        : "r"(a[mf][0]), "r"(a[mf][1]), "r"(a[mf][2]), "r"(a[mf][3]),
                          "r"(b[nf][0]), "r"(b[nf][1]));
                }
        }
        __syncthreads();
    }

    const int mbase = row0 + wm * (BM / 2);
    const int nbase = col0 + wn * (BN / 4);
    #pragma unroll
    for (int mf = 0; mf < MFRAG; mf++) {
        #pragma unroll
        for (int hr = 0; hr < 2; hr++) {
            int m = mbase + mf * 16 + (lane >> 2) + hr * 8;
            #pragma unroll
            for (int nf = 0; nf < NFRAG; nf++) {
                #pragma unroll
                for (int e = 0; e < 2; e++) {
                    int n = nbase + nf * 8 + (lane & 3) * 2 + e;
                    if (n < N) {
                        float v = acc[mf][nf][hr * 2 + e];
                        if (bias) v += bias[n];
                        if (mode == 3) {
                            int tt = m >> 7, bb = m & 127;
                            float mk = (tt < lengths[bb] - 1) ? 1.f : 0.f;
                            C[((size_t)bb * Tc + tt) * Vc + n] = v * mk;
                        } else {
                            if (C)   C[(size_t)m * ldc + n] = v;
                            if (C16) C16[(size_t)m * ld16 + n] = __float2half_rn(v);
                        }
                    }
                }
            }
        }
    }
}

// ---------------- support kernels -------------------------------------------

__global__ void f32to16_kernel(const float* __restrict__ in, __half* __restrict__ out, int n2) {
    int i = blockIdx.x * blockDim.x + threadIdx.x;
    if (i < n2) {
        float2 v = ((const float2*)in)[i];
        ((__half2*)out)[i] = __floats2half2_rn(v.x, v.y);
    }
}

__global__ void transpose16_kernel(const float* __restrict__ in, __half* __restrict__ out,
                                   int K, int N, int out_ld, int k_off) {
    __shared__ float tile[32][33];
    int kb = blockIdx.y * 32, nb = blockIdx.x * 32;
    int x = threadIdx.x, y = threadIdx.y;
    #pragma unroll
    for (int j = 0; j < 32; j += 8) {
        int k = kb + y + j, n = nb + x;
        tile[y + j][x] = (k < K && n < N) ? in[(size_t)k * N + n] : 0.f;
    }
    __syncthreads();
    #pragma unroll
    for (int j = 0; j < 32; j += 8) {
        int n = nb + y + j, k = kb + x;
        if (n < N && k < K) out[(size_t)n * out_ld + k_off + k] = __float2half_rn(tile[x][y + j]);
    }
}

__global__ void clspad_kernel() {
    int i = blockIdx.x * blockDim.x + threadIdx.x;
    int total = (VPAD2 - Vc) * Hc;
    if (i < total) g_clsT[(size_t)Vc * Hc + i] = __float2half_rn(0.f);
}

__global__ void bias_prep_kernel(const float* __restrict__ bi, const float* __restrict__ bh,
                                 const float* __restrict__ db, const float* __restrict__ bb) {
    int i = blockIdx.x * blockDim.x + threadIdx.x;
    if (i < 4 * Hc) g_bcat[i] = bi[i] + bh[i];
    if (i < NDB) g_dbbias[i] = (i < Ac) ? db[i] : bb[i - Ac];
}

__global__ void mean_kernel(const float* __restrict__ f) {
    int idx = blockIdx.x * blockDim.x + threadIdx.x;
    if (idx >= Bc * Dc) return;
    int b = idx / Dc, d = idx % Dc;
    const float* p = f + (size_t)b * Pc * Dc + d;
    float s = 0.f;
    #pragma unroll 4
    for (int i = 0; i < Pc; i++) s += p[(size_t)i * Dc];
    g_meanf16[idx] = __float2half_rn(s * (1.0f / Pc));
}

__global__ void embed_kernel(const float* __restrict__ emb, const int* __restrict__ cap) {
    int idx = blockIdx.x * blockDim.x + threadIdx.x;
    if (idx >= Bc * Tc * Ec) return;
    int j = idx % Ec;
    int bt = idx / Ec;
    int t = bt % Tc;
    int b = bt / Tc;
    int tok = cap[b * TMAXc + t];
    g_eseq16[idx] = __float2half_rn(emb[(size_t)tok * Ec + j]);
}

// ---------------- launcher ---------------------------------------------------

static void transL(const float* in, __half* out, int K, int N, int out_ld, int k_off) {
    dim3 grid((N + 31) / 32, (K + 31) / 32);
    transpose16_kernel<<<grid, dim3(32, 8)>>>(in, out, K, N, out_ld, k_off);
}

extern "C" void kernel_launch(void* const* d_in, const int* in_sizes, int n_in,
                              void* d_out, int out_size) {
    const float* features = (const float*)d_in[0];
    const int*   captions = (const int*)d_in[1];
    const int*   lengths  = (const int*)d_in[2];
    const float* emb      = (const float*)d_in[3];
    const float* h_fc_w   = (const float*)d_in[4];
    const float* h_fc_b   = (const float*)d_in[5];
    const float* c_fc_w   = (const float*)d_in[6];
    const float* c_fc_b   = (const float*)d_in[7];
    const float* enc_w    = (const float*)d_in[8];
    const float* enc_b    = (const float*)d_in[9];
    const float* dec_w    = (const float*)d_in[10];
    const float* dec_b    = (const float*)d_in[11];
    const float* att_w    = (const float*)d_in[12];
    const float* att_b    = (const float*)d_in[13];
    const float* beta_w   = (const float*)d_in[14];
    const float* beta_b   = (const float*)d_in[15];
    const float* w_ih     = (const float*)d_in[16];
    const float* b_ih     = (const float*)d_in[17];
    const float* w_hh     = (const float*)d_in[18];
    const float* b_hh     = (const float*)d_in[19];
    const float* cls_w    = (const float*)d_in[20];
    const float* cls_b    = (const float*)d_in[21];

    float* out = (float*)d_out;
    float* y_out = out;                               // (B, T, V)
    float* a_out = out + (size_t)Bc * Tc * Vc;        // (B, T, P)

    __half *feat16, *meanf16, *h16, *hn16, *att1_16;
    __half *hfcT, *cfcT, *encT, *dbT, *wcatT, *clsT;
    float *cst;
    cudaGetSymbolAddress((void**)&feat16,  g_feat16);
    cudaGetSymbolAddress((void**)&meanf16, g_meanf16);
    cudaGetSymbolAddress((void**)&h16,     g_h16);
    cudaGetSymbolAddress((void**)&hn16,    g_hn16);
    cudaGetSymbolAddress((void**)&att1_16, g_att1_16);
    cudaGetSymbolAddress((void**)&hfcT,    g_hfcT);
    cudaGetSymbolAddress((void**)&cfcT,    g_cfcT);
    cudaGetSymbolAddress((void**)&encT,    g_encT);
    cudaGetSymbolAddress((void**)&dbT,     g_dbT);
    cudaGetSymbolAddress((void**)&wcatT,   g_wcatT);
    cudaGetSymbolAddress((void**)&clsT,    g_clsT);
    cudaGetSymbolAddress((void**)&cst,     g_c);

    // persistent-kernel grid: full residency (R11/R16 config — best measured)
    int smcount = 0, occ = 0;
    cudaDeviceGetAttribute(&smcount, cudaDevAttrMultiProcessorCount, 0);
    cudaOccupancyMaxActiveBlocksPerMultiprocessor(&occ, step_loop_kernel, 256, 0);
    if (occ < 1) occ = 1;
    if (occ > 2) occ = 2;
    int nb = smcount * occ;

    // ---- prologue --------------------------------------------------------
    f32to16_kernel<<<((Bc * Pc * Dc / 2) + 255) / 256, 256>>>(features, feat16, Bc * Pc * Dc / 2);
    transL(h_fc_w, hfcT, Dc, Hc, Dc, 0);
    transL(c_fc_w, cfcT, Dc, Hc, Dc, 0);
    transL(enc_w,  encT, Dc, Ac, Dc, 0);
    transL(dec_w,  dbT, Hc, Ac, Hc, 0);
    transL(beta_w, dbT + (size_t)Ac * Hc, Hc, Dc, Hc, 0);
    transL(w_ih,   wcatT, Dc + Ec, 4 * Hc, KCAT, 0);
    transL(w_hh,   wcatT, Hc, 4 * Hc, KCAT, Dc + Ec);
    transL(cls_w,  clsT, Hc, Vc, Hc, 0);
    clspad_kernel<<<(((VPAD2 - Vc) * Hc) + 255) / 256, 256>>>();
    bias_prep_kernel<<<(NDB + 255) / 256, 256>>>(b_ih, b_hh, dec_b, beta_b);
    mean_kernel<<<(Bc * Dc + 255) / 256, 256>>>(features);
    embed_kernel<<<(Bc * Tc * Ec + 255) / 256, 256>>>(emb, captions);

    // h0 / c0 / att1
    {
        dim3 g1(Hc / 64, Bc / 64);
        gemm_mma<64, 64><<<g1, 256>>>(meanf16, hfcT, h_fc_b, nullptr, h16, Bc, Hc, Dc, 0, Hc, 0, nullptr);
        gemm_mma<64, 64><<<g1, 256>>>(meanf16, cfcT, c_fc_b, cst, nullptr, Bc, Hc, Dc, Hc, 0, 0, nullptr);
        dim3 g2(Ac / 128, (Bc * Pc) / 64);
        gemm_mma<64, 128><<<g2, 256>>>(feat16, encT, enc_b, nullptr, att1_16, Bc * Pc, Ac, Dc, 0, Ac, 0, nullptr);
    }

    // ---- persistent 19-step loop -----------------------------------------
    step_loop_kernel<<<nb, 256>>>(att_w, att_b, lengths, a_out);

    // ---- batched cls over all steps: (Tc*Bc, Vc) = hn_all @ clsT ---------
    {
        dim3 g3((Vc + 127) / 128, (Tc * Bc) / 64);
        gemm_mma<64, 128><<<g3, 256>>>(hn16, clsT, cls_b, y_out, nullptr,
                                       Tc * Bc, Vc, Hc, 0, 0, 3, lengths);
    }
}